// round 4
// baseline (speedup 1.0000x reference)
#include <cuda_runtime.h>
#include <cstdint>
#include <math.h>

typedef unsigned long long ull;

#define N_TOK 8192
#define DIM   1024
#define HDIM  4096
#define NEXP  8
#define NSLOT 16384           // N_TOK * 2
#define CAP   17408           // 16384 + 8*128 padding, multiple of 128
#define MAXTILES 136          // CAP / 128

// -------- scratch (static __device__ arrays: no runtime allocation) --------
__device__ float g_H[(size_t)CAP * HDIM];     // 285 MB  relu^2(x @ w_fc^T)
__device__ float g_ys[(size_t)NSLOT * DIM];   // 64 MB   per-slot weighted expert output
__device__ int   g_rowTok[CAP];
__device__ int   g_rowSlot[CAP];
__device__ float g_rowW[CAP];
__device__ int   g_slotE[NSLOT];
__device__ float g_slotW[NSLOT];
__device__ int   g_cnt[NEXP];
__device__ int   g_cursor[NEXP];
__device__ int   g_padOff[NEXP + 1];
__device__ int   g_tileE[MAXTILES];
__device__ float g_probSum[NEXP];

// -------- packed f32x2 helpers (FFMA2: 2 FMAs per instruction) --------
__device__ __forceinline__ ull pack2(float v) {
    ull r;
    asm("mov.b64 %0, {%1, %1};" : "=l"(r) : "f"(v));
    return r;
}
__device__ __forceinline__ void fma2(ull &c, ull a, ull b) {
    asm("fma.rn.f32x2 %0, %1, %2, %0;" : "+l"(c) : "l"(a), "l"(b));
}
__device__ __forceinline__ float2 unpack2(ull v) {
    float2 r;
    asm("mov.b64 {%0, %1}, %2;" : "=f"(r.x), "=f"(r.y) : "l"(v));
    return r;
}

// ---------------------------------------------------------------------------
// K0: reset counters + invalidate row list
// ---------------------------------------------------------------------------
__global__ void k_init() {
    int i = blockIdx.x * blockDim.x + threadIdx.x;
    if (i < CAP) g_rowTok[i] = -1;
    if (i < NEXP) { g_cnt[i] = 0; g_cursor[i] = 0; g_probSum[i] = 0.f; }
}

// ---------------------------------------------------------------------------
// K1: gating — one warp per token. fp32 logits, softmax, top-2, weights.
// ---------------------------------------------------------------------------
__global__ __launch_bounds__(256) void k_gate(const float* __restrict__ x,
                                              const float* __restrict__ gw) {
    __shared__ float sProb[NEXP];
    __shared__ int   sCnt[NEXP];
    int tid = threadIdx.x;
    if (tid < NEXP) { sProb[tid] = 0.f; sCnt[tid] = 0; }
    __syncthreads();

    int warp = tid >> 5, lane = tid & 31;
    int n = blockIdx.x * 8 + warp;          // grid = 1024 blocks -> n < 8192

    const float* xr = x + (size_t)n * DIM;
    float xv[32];
    #pragma unroll
    for (int j = 0; j < 32; j++) xv[j] = xr[j * 32 + lane];

    float logit[NEXP];
    #pragma unroll
    for (int e = 0; e < NEXP; e++) {
        const float* g = gw + e * DIM;
        float s = 0.f;
        #pragma unroll
        for (int j = 0; j < 32; j++) s += xv[j] * g[j * 32 + lane];
        #pragma unroll
        for (int o = 16; o; o >>= 1) s += __shfl_xor_sync(0xffffffffu, s, o);
        logit[e] = s;
    }

    if (lane == 0) {
        float m = logit[0];
        #pragma unroll
        for (int e = 1; e < NEXP; e++) m = fmaxf(m, logit[e]);
        float p[NEXP]; float Z = 0.f;
        #pragma unroll
        for (int e = 0; e < NEXP; e++) { p[e] = expf(logit[e] - m); Z += p[e]; }
        float inv = 1.f / Z;
        #pragma unroll
        for (int e = 0; e < NEXP; e++) p[e] *= inv;

        int i1 = 0;
        #pragma unroll
        for (int e = 1; e < NEXP; e++) if (p[e] > p[i1]) i1 = e;
        int i2 = (i1 == 0) ? 1 : 0;
        #pragma unroll
        for (int e = 0; e < NEXP; e++) if (e != i1 && p[e] > p[i2]) i2 = e;

        float s2 = p[i1] + p[i2];
        g_slotE[2 * n]     = i1;  g_slotW[2 * n]     = p[i1] / s2;
        g_slotE[2 * n + 1] = i2;  g_slotW[2 * n + 1] = p[i2] / s2;

        atomicAdd(&sCnt[i1], 1);
        atomicAdd(&sCnt[i2], 1);
        #pragma unroll
        for (int e = 0; e < NEXP; e++) atomicAdd(&sProb[e], p[e]);
    }
    __syncthreads();
    if (tid < NEXP) {
        atomicAdd(&g_probSum[tid], sProb[tid]);
        atomicAdd(&g_cnt[tid], sCnt[tid]);
    }
}

// ---------------------------------------------------------------------------
// K2: scan counts -> padded offsets, tile->expert map, balance loss
// ---------------------------------------------------------------------------
__global__ void k_scan(float* out, int out_size) {
    if (threadIdx.x != 0 || blockIdx.x != 0) return;
    int off = 0;
    for (int e = 0; e < NEXP; e++) {
        g_padOff[e] = off;
        off += ((g_cnt[e] + 127) >> 7) << 7;
    }
    g_padOff[NEXP] = off;
    for (int e = 0; e < NEXP; e++)
        for (int t = g_padOff[e] >> 7; t < (g_padOff[e + 1] >> 7); t++) g_tileE[t] = e;
    for (int t = off >> 7; t < MAXTILES; t++) g_tileE[t] = -1;

    if (out_size > N_TOK * DIM) {
        float l = 0.f;
        for (int e = 0; e < NEXP; e++) l += g_probSum[e] * (float)g_cnt[e];
        out[(size_t)N_TOK * DIM] = l * (float)NEXP / ((float)N_TOK * (float)N_TOK);
    }
}

// ---------------------------------------------------------------------------
// K3: scatter slots into per-expert padded segments
// ---------------------------------------------------------------------------
__global__ void k_scatter() {
    int s = blockIdx.x * blockDim.x + threadIdx.x;
    if (s >= NSLOT) return;
    int e = g_slotE[s];
    int pos = g_padOff[e] + atomicAdd(&g_cursor[e], 1);
    g_rowTok[pos]  = s >> 1;
    g_rowSlot[pos] = s;
    g_rowW[pos]    = g_slotW[s];
}

// ---------------------------------------------------------------------------
// GEMM: C[128x128] tile, both operands K-major (C = A * W^T), fp32 via FFMA2.
// MODE 0: A = x rows gathered by g_rowTok, W = w_fc[e],  out = relu^2 -> g_H
// MODE 1: A = g_H rows (direct),           W = w_proj[e], out = w * y -> g_ys
// Thread: 8 rows x (4 + 4) cols, accumulated as packed f32x2 pairs.
// ---------------------------------------------------------------------------
template<int KD, int MODE>
__global__ __launch_bounds__(256) void k_gemm(const float* __restrict__ Aglob,
                                              const float* __restrict__ Wglob) {
    int e = g_tileE[blockIdx.y];
    if (e < 0) return;

    __shared__ __align__(16) float As[16][132];
    __shared__ __align__(16) float Bs[16][132];

    const int tid = threadIdx.x;
    const int ldr = tid >> 2;        // 0..63
    const int ldc = tid & 3;         // float4 column
    const int rowBase = blockIdx.y << 7;
    const int colBase = blockIdx.x << 7;

    const float* Wbase = Wglob + (size_t)e * HDIM * DIM;

    bool v0 = true, v1 = true;
    const float4 *a0, *a1;
    if (MODE == 0) {
        int t0 = g_rowTok[rowBase + ldr];
        int t1 = g_rowTok[rowBase + ldr + 64];
        v0 = t0 >= 0; v1 = t1 >= 0;
        a0 = (const float4*)(Aglob + (size_t)(v0 ? t0 : 0) * KD) + ldc;
        a1 = (const float4*)(Aglob + (size_t)(v1 ? t1 : 0) * KD) + ldc;
    } else {
        a0 = (const float4*)(g_H + (size_t)(rowBase + ldr) * KD) + ldc;
        a1 = (const float4*)(g_H + (size_t)(rowBase + ldr + 64) * KD) + ldc;
    }
    const float4* b0 = (const float4*)(Wbase + (size_t)(colBase + ldr) * KD) + ldc;
    const float4* b1 = (const float4*)(Wbase + (size_t)(colBase + ldr + 64) * KD) + ldc;

    const int tx = tid & 15, ty = tid >> 4;

    ull acc[8][4];
    #pragma unroll
    for (int i = 0; i < 8; i++) {
        acc[i][0] = 0ull; acc[i][1] = 0ull; acc[i][2] = 0ull; acc[i][3] = 0ull;
    }

    for (int k0 = 0; k0 < KD; k0 += 16) {
        float4 va0 = v0 ? a0[k0 >> 2] : make_float4(0.f, 0.f, 0.f, 0.f);
        float4 va1 = v1 ? a1[k0 >> 2] : make_float4(0.f, 0.f, 0.f, 0.f);
        float4 vb0 = b0[k0 >> 2];
        float4 vb1 = b1[k0 >> 2];
        int kk = ldc << 2;
        As[kk + 0][ldr] = va0.x; As[kk + 1][ldr] = va0.y;
        As[kk + 2][ldr] = va0.z; As[kk + 3][ldr] = va0.w;
        As[kk + 0][ldr + 64] = va1.x; As[kk + 1][ldr + 64] = va1.y;
        As[kk + 2][ldr + 64] = va1.z; As[kk + 3][ldr + 64] = va1.w;
        Bs[kk + 0][ldr] = vb0.x; Bs[kk + 1][ldr] = vb0.y;
        Bs[kk + 2][ldr] = vb0.z; Bs[kk + 3][ldr] = vb0.w;
        Bs[kk + 0][ldr + 64] = vb1.x; Bs[kk + 1][ldr + 64] = vb1.y;
        Bs[kk + 2][ldr + 64] = vb1.z; Bs[kk + 3][ldr + 64] = vb1.w;
        __syncthreads();

        #pragma unroll
        for (int k = 0; k < 16; k++) {
            float4 aA = *(const float4*)&As[k][ty * 8];
            float4 aB = *(const float4*)&As[k][ty * 8 + 4];
            ull ap[8];
            ap[0] = pack2(aA.x); ap[1] = pack2(aA.y);
            ap[2] = pack2(aA.z); ap[3] = pack2(aA.w);
            ap[4] = pack2(aB.x); ap[5] = pack2(aB.y);
            ap[6] = pack2(aB.z); ap[7] = pack2(aB.w);
            ull bv0 = *(const ull*)&Bs[k][tx * 4];
            ull bv1 = *(const ull*)&Bs[k][tx * 4 + 2];
            ull bv2 = *(const ull*)&Bs[k][tx * 4 + 64];
            ull bv3 = *(const ull*)&Bs[k][tx * 4 + 66];
            #pragma unroll
            for (int i = 0; i < 8; i++) {
                fma2(acc[i][0], ap[i], bv0);
                fma2(acc[i][1], ap[i], bv1);
                fma2(acc[i][2], ap[i], bv2);
                fma2(acc[i][3], ap[i], bv3);
            }
        }
        __syncthreads();
    }

    // epilogue
    #pragma unroll
    for (int i = 0; i < 8; i++) {
        int r = rowBase + ty * 8 + i;
        float2 p0 = unpack2(acc[i][0]);
        float2 p1 = unpack2(acc[i][1]);
        float2 p2 = unpack2(acc[i][2]);
        float2 p3 = unpack2(acc[i][3]);
        if (MODE == 0) {
            float4 o0, o1;
            float t;
            t = fmaxf(p0.x, 0.f); o0.x = t * t;
            t = fmaxf(p0.y, 0.f); o0.y = t * t;
            t = fmaxf(p1.x, 0.f); o0.z = t * t;
            t = fmaxf(p1.y, 0.f); o0.w = t * t;
            t = fmaxf(p2.x, 0.f); o1.x = t * t;
            t = fmaxf(p2.y, 0.f); o1.y = t * t;
            t = fmaxf(p3.x, 0.f); o1.z = t * t;
            t = fmaxf(p3.y, 0.f); o1.w = t * t;
            float* dst = g_H + (size_t)r * HDIM + colBase + tx * 4;
            *(float4*)dst = o0;
            *(float4*)(dst + 64) = o1;
        } else {
            int tok = g_rowTok[r];
            if (tok < 0) continue;
            float w = g_rowW[r];
            int slot = g_rowSlot[r];
            float4 o0, o1;
            o0.x = w * p0.x; o0.y = w * p0.y; o0.z = w * p1.x; o0.w = w * p1.y;
            o1.x = w * p2.x; o1.y = w * p2.y; o1.z = w * p3.x; o1.w = w * p3.y;
            float* dst = g_ys + (size_t)slot * DIM + colBase + tx * 4;
            *(float4*)dst = o0;
            *(float4*)(dst + 64) = o1;
        }
    }
}

// ---------------------------------------------------------------------------
// K6: combine the two slots per token into the output
// ---------------------------------------------------------------------------
__global__ void k_combine(float* __restrict__ out) {
    int i = blockIdx.x * blockDim.x + threadIdx.x;   // over N_TOK * DIM/4
    const int PR = DIM / 4;                          // float4 per row
    if (i >= N_TOK * PR) return;
    int n = i / PR;
    int c = i - n * PR;
    const float4* ys = (const float4*)g_ys;
    float4 a = ys[(size_t)(2 * n) * PR + c];
    float4 b = ys[(size_t)(2 * n + 1) * PR + c];
    float4 o;
    o.x = a.x + b.x; o.y = a.y + b.y; o.z = a.z + b.z; o.w = a.w + b.w;
    ((float4*)out)[(size_t)n * PR + c] = o;
}

// ---------------------------------------------------------------------------
extern "C" void kernel_launch(void* const* d_in, const int* in_sizes, int n_in,
                              void* d_out, int out_size) {
    const float* x   = (const float*)d_in[0];   // [8192, 1024]
    const float* gw  = (const float*)d_in[1];   // [8, 1024]
    const float* wfc = (const float*)d_in[2];   // [8, 4096, 1024]
    const float* wpj = (const float*)d_in[3];   // [8, 1024, 4096]
    float* out = (float*)d_out;

    k_init<<<(CAP + 255) / 256, 256>>>();
    k_gate<<<N_TOK / 8, 256>>>(x, gw);
    k_scan<<<1, 32>>>(out, out_size);
    k_scatter<<<NSLOT / 256, 256>>>();

    dim3 g1(HDIM / 128, MAXTILES);   // 32 x 136
    k_gemm<DIM, 0><<<g1, 256>>>(x, wfc);

    dim3 g2(DIM / 128, MAXTILES);    // 8 x 136
    k_gemm<HDIM, 1><<<g2, 256>>>(nullptr, wpj);

    k_combine<<<(N_TOK * (DIM / 4) + 255) / 256, 256>>>(out);
}

// round 7
// speedup vs baseline: 1.1545x; 1.1545x over previous
#include <cuda_runtime.h>
#include <cstdint>
#include <math.h>

#define N_TOK 8192
#define DIM   1024
#define HDIM  4096
#define NEXP  8
#define NSLOT 16384
#define CAP   17408            // 16384 + 8*128 pad (per-expert pad to 128)
#define MAXTILES 136           // CAP / 128
#define LDS_STRIDE 36          // floats per smem row (32 + 4 pad: conflict-free frags)
#define STG_FLOATS (2 * 128 * LDS_STRIDE)   // A + B per stage

// ---------------- scratch (static __device__: no runtime alloc) ------------
__device__ float g_H  [(size_t)CAP   * HDIM];    // relu^2(x @ w_fc^T), fp32
__device__ float g_ys [(size_t)NSLOT * DIM];     // per-slot weighted expert out
__device__ int   g_rowTok[CAP];
__device__ int   g_rowSlot[CAP];
__device__ float g_rowW[CAP];
__device__ int   g_slotE[NSLOT];
__device__ float g_slotW[NSLOT];
__device__ int   g_cnt[NEXP];
__device__ int   g_cursor[NEXP];
__device__ int   g_padOff[NEXP + 1];
__device__ int   g_tileE[MAXTILES];
__device__ float g_probSum[NEXP];

// ---------------- helpers ---------------------------------------------------
__device__ __forceinline__ uint32_t smem_to_u32(const void* p) {
    uint32_t a;
    asm("{ .reg .u64 t; cvta.to.shared.u64 t, %1; cvt.u32.u64 %0, t; }"
        : "=r"(a) : "l"(p));
    return a;
}
__device__ __forceinline__ void cpasync16(uint32_t s, const void* g) {
    asm volatile("cp.async.cg.shared.global [%0], [%1], 16;" :: "r"(s), "l"(g) : "memory");
}
__device__ __forceinline__ uint32_t f2tf32(float x) {
    uint32_t u;
    asm("cvt.rna.tf32.f32 %0, %1;" : "=r"(u) : "f"(x));
    return u;
}
__device__ __forceinline__ void mma_tf32(float* c, const uint32_t* a, const uint32_t* b) {
    asm volatile(
        "mma.sync.aligned.m16n8k8.row.col.f32.tf32.tf32.f32 "
        "{%0,%1,%2,%3}, {%4,%5,%6,%7}, {%8,%9}, {%0,%1,%2,%3};"
        : "+f"(c[0]), "+f"(c[1]), "+f"(c[2]), "+f"(c[3])
        : "r"(a[0]), "r"(a[1]), "r"(a[2]), "r"(a[3]), "r"(b[0]), "r"(b[1]));
}

// ---------------- K0: reset -------------------------------------------------
__global__ void k_init() {
    int i = blockIdx.x * blockDim.x + threadIdx.x;
    if (i < CAP) g_rowTok[i] = -1;
    if (i < NEXP) { g_cnt[i] = 0; g_cursor[i] = 0; g_probSum[i] = 0.f; }
}

// ---------------- K1: gating (exact fp32) ----------------------------------
__global__ __launch_bounds__(256) void k_gate(const float* __restrict__ x,
                                              const float* __restrict__ gw) {
    __shared__ float sProb[NEXP];
    __shared__ int   sCnt[NEXP];
    int tid = threadIdx.x;
    if (tid < NEXP) { sProb[tid] = 0.f; sCnt[tid] = 0; }
    __syncthreads();
    int warp = tid >> 5, lane = tid & 31;
    int n = blockIdx.x * 8 + warp;
    const float* xr = x + (size_t)n * DIM;
    float xv[32];
    #pragma unroll
    for (int j = 0; j < 32; j++) xv[j] = xr[j * 32 + lane];
    float logit[NEXP];
    #pragma unroll
    for (int e = 0; e < NEXP; e++) {
        const float* g = gw + e * DIM;
        float s = 0.f;
        #pragma unroll
        for (int j = 0; j < 32; j++) s += xv[j] * g[j * 32 + lane];
        #pragma unroll
        for (int o = 16; o; o >>= 1) s += __shfl_xor_sync(0xffffffffu, s, o);
        logit[e] = s;
    }
    if (lane == 0) {
        float m = logit[0];
        #pragma unroll
        for (int e = 1; e < NEXP; e++) m = fmaxf(m, logit[e]);
        float p[NEXP]; float Z = 0.f;
        #pragma unroll
        for (int e = 0; e < NEXP; e++) { p[e] = expf(logit[e] - m); Z += p[e]; }
        float inv = 1.f / Z;
        #pragma unroll
        for (int e = 0; e < NEXP; e++) p[e] *= inv;
        int i1 = 0;
        #pragma unroll
        for (int e = 1; e < NEXP; e++) if (p[e] > p[i1]) i1 = e;
        int i2 = (i1 == 0) ? 1 : 0;
        #pragma unroll
        for (int e = 0; e < NEXP; e++) if (e != i1 && p[e] > p[i2]) i2 = e;
        float s2 = p[i1] + p[i2];
        g_slotE[2 * n]     = i1;  g_slotW[2 * n]     = p[i1] / s2;
        g_slotE[2 * n + 1] = i2;  g_slotW[2 * n + 1] = p[i2] / s2;
        atomicAdd(&sCnt[i1], 1);
        atomicAdd(&sCnt[i2], 1);
        #pragma unroll
        for (int e = 0; e < NEXP; e++) atomicAdd(&sProb[e], p[e]);
    }
    __syncthreads();
    if (tid < NEXP) {
        atomicAdd(&g_probSum[tid], sProb[tid]);
        atomicAdd(&g_cnt[tid], sCnt[tid]);
    }
}

// ---------------- K2: scan + tile map + balance loss ------------------------
__global__ void k_scan(float* out, int out_size) {
    if (threadIdx.x != 0 || blockIdx.x != 0) return;
    int off = 0;
    for (int e = 0; e < NEXP; e++) {
        g_padOff[e] = off;
        off += ((g_cnt[e] + 127) >> 7) << 7;
    }
    g_padOff[NEXP] = off;
    for (int e = 0; e < NEXP; e++)
        for (int t = g_padOff[e] >> 7; t < (g_padOff[e + 1] >> 7); t++) g_tileE[t] = e;
    for (int t = off >> 7; t < MAXTILES; t++) g_tileE[t] = -1;
    if (out_size > N_TOK * DIM) {
        float l = 0.f;
        for (int e = 0; e < NEXP; e++) l += g_probSum[e] * (float)g_cnt[e];
        out[(size_t)N_TOK * DIM] = l * (float)NEXP / ((float)N_TOK * (float)N_TOK);
    }
}

// ---------------- K3: scatter -----------------------------------------------
__global__ void k_scatter() {
    int s = blockIdx.x * blockDim.x + threadIdx.x;
    if (s >= NSLOT) return;
    int e = g_slotE[s];
    int pos = g_padOff[e] + atomicAdd(&g_cursor[e], 1);
    g_rowTok[pos]  = s >> 1;
    g_rowSlot[pos] = s;
    g_rowW[pos]    = g_slotW[s];
}

// ---------------------------------------------------------------------------
// tf32 mma.sync GEMM: 128x128 CTA tile, K-stage 32, 3-stage cp.async pipeline.
// Both operands K-major (C = A * W^T). Warp tile 64x32 (8 warps, 2x4).
// MODE 0: A = x rows gathered via g_rowTok, W = w_fc[e],  epi relu^2 -> g_H
// MODE 1: A = g_H rows (direct),            W = w_proj[e], epi *rowW  -> g_ys
// ---------------------------------------------------------------------------
template<int KD, int MODE>
__global__ void __launch_bounds__(256) k_mma(const float* __restrict__ Ag,
                                             const float* __restrict__ Wg) {
    int e = g_tileE[blockIdx.y];
    if (e < 0) return;
    extern __shared__ float smem[];   // 3 * STG_FLOATS floats
    const int tid = threadIdx.x;
    const int rowBase = blockIdx.y << 7;
    const int colBase = blockIdx.x << 7;

    // ---- load mapping: thread owns one A row + one B row, half the K-stage
    const int ldRow = tid >> 1;
    const int ldK   = (tid & 1) * 16;
    const float* aSrc;
    if (MODE == 0) {
        int tok = g_rowTok[rowBase + ldRow];
        if (tok < 0) tok = 0;                       // pad rows: valid dummy data
        aSrc = Ag + (size_t)tok * KD + ldK;
    } else {
        aSrc = g_H + (size_t)(rowBase + ldRow) * KD + ldK;
    }
    const float* bSrc = Wg + (size_t)e * ((size_t)HDIM * DIM)
                      + (size_t)(colBase + ldRow) * KD + ldK;

    const uint32_t sb = smem_to_u32(smem);
    const uint32_t aDst = sb + (ldRow * LDS_STRIDE + ldK) * 4;
    const uint32_t bDst = aDst + 128 * LDS_STRIDE * 4;

    const int T = KD / 32;

    // prologue: stages 0, 1
    #pragma unroll
    for (int t = 0; t < 2; t++) {
        uint32_t off = t * STG_FLOATS * 4;
        #pragma unroll
        for (int j = 0; j < 4; j++) {
            cpasync16(aDst + off + j * 16, aSrc + t * 32 + j * 4);
            cpasync16(bDst + off + j * 16, bSrc + t * 32 + j * 4);
        }
        asm volatile("cp.async.commit_group;" ::: "memory");
    }

    // ---- compute mapping
    const int wid = tid >> 5, lane = tid & 31;
    const int wm = wid >> 2, wn = wid & 3;          // warp tile: rows wm*64, cols wn*32
    const int qr = lane >> 2, qc = lane & 3;

    float acc[4][4][4];
    #pragma unroll
    for (int i = 0; i < 4; i++)
        #pragma unroll
        for (int j = 0; j < 4; j++) {
            acc[i][j][0] = 0.f; acc[i][j][1] = 0.f;
            acc[i][j][2] = 0.f; acc[i][j][3] = 0.f;
        }

    for (int jt = 0; jt < T; jt++) {
        if (jt + 1 < T) asm volatile("cp.async.wait_group 1;" ::: "memory");
        else            asm volatile("cp.async.wait_group 0;" ::: "memory");
        __syncthreads();

        if (jt + 2 < T) {
            uint32_t off = ((jt + 2) % 3) * STG_FLOATS * 4;
            #pragma unroll
            for (int j = 0; j < 4; j++) {
                cpasync16(aDst + off + j * 16, aSrc + (jt + 2) * 32 + j * 4);
                cpasync16(bDst + off + j * 16, bSrc + (jt + 2) * 32 + j * 4);
            }
            asm volatile("cp.async.commit_group;" ::: "memory");
        }

        const float* As = smem + (jt % 3) * STG_FLOATS;
        const float* Bs = As + 128 * LDS_STRIDE;
        const float* Ap = As + (wm * 64 + qr) * LDS_STRIDE + qc;
        const float* Bp = Bs + (wn * 32 + qr) * LDS_STRIDE + qc;

        #pragma unroll
        for (int kb = 0; kb < 4; kb++) {
            const int k0 = kb * 8;
            uint32_t a[4][4], b[4][2];
            #pragma unroll
            for (int mt = 0; mt < 4; mt++) {
                const float* p = Ap + mt * 16 * LDS_STRIDE + k0;
                a[mt][0] = f2tf32(p[0]);
                a[mt][1] = f2tf32(p[8 * LDS_STRIDE]);
                a[mt][2] = f2tf32(p[4]);
                a[mt][3] = f2tf32(p[8 * LDS_STRIDE + 4]);
            }
            #pragma unroll
            for (int nt = 0; nt < 4; nt++) {
                const float* p = Bp + nt * 8 * LDS_STRIDE + k0;
                b[nt][0] = f2tf32(p[0]);
                b[nt][1] = f2tf32(p[4]);
            }
            #pragma unroll
            for (int mt = 0; mt < 4; mt++)
                #pragma unroll
                for (int nt = 0; nt < 4; nt++)
                    mma_tf32(acc[mt][nt], a[mt], b[nt]);
        }
    }

    // ---- epilogue. Frag layout: c0,c1 -> row qr, cols 2qc,2qc+1; c2,c3 -> row qr+8
    #pragma unroll
    for (int mt = 0; mt < 4; mt++) {
        const int r0 = rowBase + wm * 64 + mt * 16 + qr;
        const int r1 = r0 + 8;
        if (MODE == 0) {
            #pragma unroll
            for (int nt = 0; nt < 4; nt++) {
                const int cg = colBase + wn * 32 + nt * 8 + 2 * qc;
                float t0 = fmaxf(acc[mt][nt][0], 0.f);
                float t1 = fmaxf(acc[mt][nt][1], 0.f);
                float t2 = fmaxf(acc[mt][nt][2], 0.f);
                float t3 = fmaxf(acc[mt][nt][3], 0.f);
                *(float2*)(g_H + (size_t)r0 * HDIM + cg) = make_float2(t0 * t0, t1 * t1);
                *(float2*)(g_H + (size_t)r1 * HDIM + cg) = make_float2(t2 * t2, t3 * t3);
            }
        } else {
            int   tok0 = g_rowTok[r0],  tok1 = g_rowTok[r1];
            float w0   = g_rowW[r0],    w1   = g_rowW[r1];
            int   sl0  = g_rowSlot[r0], sl1  = g_rowSlot[r1];
            #pragma unroll
            for (int nt = 0; nt < 4; nt++) {
                const int cg = colBase + wn * 32 + nt * 8 + 2 * qc;
                if (tok0 >= 0)
                    *(float2*)(g_ys + (size_t)sl0 * DIM + cg) =
                        make_float2(w0 * acc[mt][nt][0], w0 * acc[mt][nt][1]);
                if (tok1 >= 0)
                    *(float2*)(g_ys + (size_t)sl1 * DIM + cg) =
                        make_float2(w1 * acc[mt][nt][2], w1 * acc[mt][nt][3]);
            }
        }
    }
}

// ---------------- K6: combine two slots per token ---------------------------
__global__ void k_combine(float* __restrict__ out) {
    int i = blockIdx.x * blockDim.x + threadIdx.x;
    const int PR = DIM / 4;
    if (i >= N_TOK * PR) return;
    int n = i / PR;
    int c = i - n * PR;
    const float4* ys = (const float4*)g_ys;
    float4 a = ys[(size_t)(2 * n) * PR + c];
    float4 b = ys[(size_t)(2 * n + 1) * PR + c];
    float4 o;
    o.x = a.x + b.x; o.y = a.y + b.y; o.z = a.z + b.z; o.w = a.w + b.w;
    ((float4*)out)[(size_t)n * PR + c] = o;
}

// ---------------------------------------------------------------------------
extern "C" void kernel_launch(void* const* d_in, const int* in_sizes, int n_in,
                              void* d_out, int out_size) {
    const float* x   = (const float*)d_in[0];   // [8192, 1024]
    const float* gw  = (const float*)d_in[1];   // [8, 1024]
    const float* wfc = (const float*)d_in[2];   // [8, 4096, 1024]
    const float* wpj = (const float*)d_in[3];   // [8, 1024, 4096]
    float* out = (float*)d_out;

    const int SMEM_BYTES = 3 * STG_FLOATS * 4;  // 110592
    cudaFuncSetAttribute(k_mma<DIM, 0>,  cudaFuncAttributeMaxDynamicSharedMemorySize, SMEM_BYTES);
    cudaFuncSetAttribute(k_mma<HDIM, 1>, cudaFuncAttributeMaxDynamicSharedMemorySize, SMEM_BYTES);

    k_init<<<CAP / 256, 256>>>();
    k_gate<<<N_TOK / 8, 256>>>(x, gw);
    k_scan<<<1, 32>>>(out, out_size);
    k_scatter<<<NSLOT / 256, 256>>>();

    dim3 g1(HDIM / 128, MAXTILES);              // 32 x 136
    k_mma<DIM, 0><<<g1, 256, SMEM_BYTES>>>(x, wfc);

    dim3 g2(DIM / 128, MAXTILES);               // 8 x 136
    k_mma<HDIM, 1><<<g2, 256, SMEM_BYTES>>>(nullptr, wpj);

    k_combine<<<(N_TOK * (DIM / 4) + 255) / 256, 256>>>(out);
}

// round 8
// speedup vs baseline: 1.6557x; 1.4341x over previous
#include <cuda_runtime.h>
#include <cstdint>
#include <math.h>

#define N_TOK 8192
#define DIM   1024
#define HDIM  4096
#define NEXP  8
#define NSLOT 16384
#define CAP   17408            // 16384 + 8*128 pad (per-expert pad to 128)
#define MAXTILES 136           // CAP / 128
#define STAGE_BYTES 16384      // (128 A rows + 128 B rows) * 16 floats * 4B
#define NSTAGE 4

// ---------------- scratch (static __device__: no runtime alloc) ------------
__device__ float g_H  [(size_t)CAP   * HDIM];    // relu^2(x @ w_fc^T), fp32
__device__ float g_ys [(size_t)NSLOT * DIM];     // per-slot weighted expert out
__device__ int   g_rowTok[CAP];
__device__ int   g_rowSlot[CAP];
__device__ float g_rowW[CAP];
__device__ int   g_slotE[NSLOT];
__device__ float g_slotW[NSLOT];
__device__ int   g_cnt[NEXP];
__device__ int   g_cursor[NEXP];
__device__ int   g_padOff[NEXP + 1];
__device__ int   g_tileE[MAXTILES];
__device__ float g_probSum[NEXP];

// ---------------- helpers ---------------------------------------------------
__device__ __forceinline__ uint32_t smem_to_u32(const void* p) {
    uint32_t a;
    asm("{ .reg .u64 t; cvta.to.shared.u64 t, %1; cvt.u32.u64 %0, t; }"
        : "=r"(a) : "l"(p));
    return a;
}
__device__ __forceinline__ void cpasync16(uint32_t s, const void* g) {
    asm volatile("cp.async.cg.shared.global [%0], [%1], 16;" :: "r"(s), "l"(g) : "memory");
}
__device__ __forceinline__ uint32_t f2tf32(uint32_t x) {
    uint32_t u;
    asm("cvt.rna.tf32.f32 %0, %1;" : "=r"(u) : "f"(__uint_as_float(x)));
    return u;
}
__device__ __forceinline__ void ldsm4(uint32_t& r0, uint32_t& r1, uint32_t& r2,
                                      uint32_t& r3, uint32_t addr) {
    asm volatile("ldmatrix.sync.aligned.m8n8.x4.shared.b16 {%0,%1,%2,%3}, [%4];"
                 : "=r"(r0), "=r"(r1), "=r"(r2), "=r"(r3) : "r"(addr));
}
__device__ __forceinline__ void mma_tf32(float* c, const uint32_t* a, const uint32_t* b) {
    asm volatile(
        "mma.sync.aligned.m16n8k8.row.col.f32.tf32.tf32.f32 "
        "{%0,%1,%2,%3}, {%4,%5,%6,%7}, {%8,%9}, {%0,%1,%2,%3};"
        : "+f"(c[0]), "+f"(c[1]), "+f"(c[2]), "+f"(c[3])
        : "r"(a[0]), "r"(a[1]), "r"(a[2]), "r"(a[3]), "r"(b[0]), "r"(b[1]));
}

// ---------------- K0: reset -------------------------------------------------
__global__ void k_init() {
    int i = blockIdx.x * blockDim.x + threadIdx.x;
    if (i < CAP) g_rowTok[i] = -1;
    if (i < NEXP) { g_cnt[i] = 0; g_cursor[i] = 0; g_probSum[i] = 0.f; }
}

// ---------------- K1: gating (exact fp32) ----------------------------------
__global__ __launch_bounds__(256) void k_gate(const float* __restrict__ x,
                                              const float* __restrict__ gw) {
    __shared__ float sProb[NEXP];
    __shared__ int   sCnt[NEXP];
    int tid = threadIdx.x;
    if (tid < NEXP) { sProb[tid] = 0.f; sCnt[tid] = 0; }
    __syncthreads();
    int warp = tid >> 5, lane = tid & 31;
    int n = blockIdx.x * 8 + warp;
    const float* xr = x + (size_t)n * DIM;
    float xv[32];
    #pragma unroll
    for (int j = 0; j < 32; j++) xv[j] = xr[j * 32 + lane];
    float logit[NEXP];
    #pragma unroll
    for (int e = 0; e < NEXP; e++) {
        const float* g = gw + e * DIM;
        float s = 0.f;
        #pragma unroll
        for (int j = 0; j < 32; j++) s += xv[j] * g[j * 32 + lane];
        #pragma unroll
        for (int o = 16; o; o >>= 1) s += __shfl_xor_sync(0xffffffffu, s, o);
        logit[e] = s;
    }
    if (lane == 0) {
        float m = logit[0];
        #pragma unroll
        for (int e = 1; e < NEXP; e++) m = fmaxf(m, logit[e]);
        float p[NEXP]; float Z = 0.f;
        #pragma unroll
        for (int e = 0; e < NEXP; e++) { p[e] = expf(logit[e] - m); Z += p[e]; }
        float inv = 1.f / Z;
        #pragma unroll
        for (int e = 0; e < NEXP; e++) p[e] *= inv;
        int i1 = 0;
        #pragma unroll
        for (int e = 1; e < NEXP; e++) if (p[e] > p[i1]) i1 = e;
        int i2 = (i1 == 0) ? 1 : 0;
        #pragma unroll
        for (int e = 0; e < NEXP; e++) if (e != i1 && p[e] > p[i2]) i2 = e;
        float s2 = p[i1] + p[i2];
        g_slotE[2 * n]     = i1;  g_slotW[2 * n]     = p[i1] / s2;
        g_slotE[2 * n + 1] = i2;  g_slotW[2 * n + 1] = p[i2] / s2;
        atomicAdd(&sCnt[i1], 1);
        atomicAdd(&sCnt[i2], 1);
        #pragma unroll
        for (int e = 0; e < NEXP; e++) atomicAdd(&sProb[e], p[e]);
    }
    __syncthreads();
    if (tid < NEXP) {
        atomicAdd(&g_probSum[tid], sProb[tid]);
        atomicAdd(&g_cnt[tid], sCnt[tid]);
    }
}

// ---------------- K2: scan + tile map + balance loss ------------------------
__global__ void k_scan(float* out, int out_size) {
    if (threadIdx.x != 0 || blockIdx.x != 0) return;
    int off = 0;
    for (int e = 0; e < NEXP; e++) {
        g_padOff[e] = off;
        off += ((g_cnt[e] + 127) >> 7) << 7;
    }
    g_padOff[NEXP] = off;
    for (int e = 0; e < NEXP; e++)
        for (int t = g_padOff[e] >> 7; t < (g_padOff[e + 1] >> 7); t++) g_tileE[t] = e;
    for (int t = off >> 7; t < MAXTILES; t++) g_tileE[t] = -1;
    if (out_size > N_TOK * DIM) {
        float l = 0.f;
        for (int e = 0; e < NEXP; e++) l += g_probSum[e] * (float)g_cnt[e];
        out[(size_t)N_TOK * DIM] = l * (float)NEXP / ((float)N_TOK * (float)N_TOK);
    }
}

// ---------------- K3: scatter -----------------------------------------------
__global__ void k_scatter() {
    int s = blockIdx.x * blockDim.x + threadIdx.x;
    if (s >= NSLOT) return;
    int e = g_slotE[s];
    int pos = g_padOff[e] + atomicAdd(&g_cursor[e], 1);
    g_rowTok[pos]  = s >> 1;
    g_rowSlot[pos] = s;
    g_rowW[pos]    = g_slotW[s];
}

// ---------------------------------------------------------------------------
// tf32 mma.sync GEMM, ldmatrix edition.
// CTA 128x128, 128 threads (4 warps, 2x2 of 64x64 warp tiles), K-stage 16,
// 4-stage cp.async pipeline, XOR-swizzled 64B smem rows (conflict-free LDSM).
// MODE 0: A = x rows gathered via g_rowTok, W = w_fc[e],  epi relu^2 -> g_H
// MODE 1: A = g_H rows (direct),            W = w_proj[e], epi *rowW  -> g_ys
// ---------------------------------------------------------------------------
template<int KD, int MODE>
__global__ void __launch_bounds__(128) k_mma(const float* __restrict__ Ag,
                                             const float* __restrict__ Wg) {
    int e = g_tileE[blockIdx.y];
    if (e < 0) return;
    extern __shared__ float smem[];   // NSTAGE * STAGE_BYTES
    const int tid = threadIdx.x;
    const int rowBase = blockIdx.y << 7;
    const int colBase = blockIdx.x << 7;

    // ---- loader mapping: thread t owns A row t and B row t (16 floats/stage)
    const float* aSrc;
    if (MODE == 0) {
        int tok = g_rowTok[rowBase + tid];
        if (tok < 0) tok = 0;                       // pad rows: valid dummy data
        aSrc = Ag + (size_t)tok * KD;
    } else {
        aSrc = g_H + (size_t)(rowBase + tid) * KD;
    }
    const float* bSrc = Wg + (size_t)e * ((size_t)HDIM * DIM)
                      + (size_t)(colBase + tid) * KD;

    const uint32_t sb = smem_to_u32(smem);
    const uint32_t wsw = (tid >> 1) & 3;            // writer swizzle
    uint32_t aOff[4];
    #pragma unroll
    for (int j = 0; j < 4; j++) aOff[j] = tid * 64 + ((j ^ wsw) << 4);

    const int T = KD / 16;

    // prologue: stages 0..2
    #pragma unroll
    for (int t = 0; t < NSTAGE - 1; t++) {
        uint32_t so = sb + t * STAGE_BYTES;
        const float* ga = aSrc + t * 16;
        const float* gb = bSrc + t * 16;
        #pragma unroll
        for (int j = 0; j < 4; j++) {
            cpasync16(so + aOff[j], ga + j * 4);
            cpasync16(so + 8192 + aOff[j], gb + j * 4);
        }
        asm volatile("cp.async.commit_group;" ::: "memory");
    }

    // ---- compute mapping
    const int wid = tid >> 5, lane = tid & 31;
    const int wm = wid >> 1, wn = wid & 1;          // 2x2 warps of 64x64
    // ldmatrix lane geometry: mat = lane/8, row-in-16 = (mat&1)*8 + lane%8
    const int mat = lane >> 3;
    const int l8  = ((mat & 1) << 3) + (lane & 7);
    const int cm  = mat >> 1;                       // chunk sub-index (0/1)
    const int rsw = (l8 >> 1) & 3;                  // reader swizzle
    const uint32_t pc0 = (uint32_t)(((0 + cm) ^ rsw) << 4);  // kb=0 chunk offset
    const uint32_t pc1 = (uint32_t)(((2 + cm) ^ rsw) << 4);  // kb=1 chunk offset
    const uint32_t aLane = (uint32_t)(wm * 4096 + l8 * 64);
    const uint32_t bLane = (uint32_t)(8192 + wn * 4096 + l8 * 64);

    float acc[4][8][4];
    #pragma unroll
    for (int i = 0; i < 4; i++)
        #pragma unroll
        for (int j = 0; j < 8; j++)
            #pragma unroll
            for (int q = 0; q < 4; q++) acc[i][j][q] = 0.f;

    for (int jt = 0; jt < T; jt++) {
        if (jt < T - 2)      asm volatile("cp.async.wait_group 2;" ::: "memory");
        else if (jt == T - 2) asm volatile("cp.async.wait_group 1;" ::: "memory");
        else                  asm volatile("cp.async.wait_group 0;" ::: "memory");
        __syncthreads();

        if (jt + NSTAGE - 1 < T) {
            int t = jt + NSTAGE - 1;
            uint32_t so = sb + (t & (NSTAGE - 1)) * STAGE_BYTES;
            const float* ga = aSrc + t * 16;
            const float* gb = bSrc + t * 16;
            #pragma unroll
            for (int j = 0; j < 4; j++) {
                cpasync16(so + aOff[j], ga + j * 4);
                cpasync16(so + 8192 + aOff[j], gb + j * 4);
            }
            asm volatile("cp.async.commit_group;" ::: "memory");
        }

        const uint32_t so = sb + (jt & (NSTAGE - 1)) * STAGE_BYTES;
        const uint32_t sA = so + aLane;
        const uint32_t sB = so + bLane;

        #pragma unroll
        for (int kb = 0; kb < 2; kb++) {
            const uint32_t pc = kb ? pc1 : pc0;
            uint32_t a[4][4], b[8][2];
            #pragma unroll
            for (int mt = 0; mt < 4; mt++) {
                ldsm4(a[mt][0], a[mt][1], a[mt][2], a[mt][3], sA + mt * 1024 + pc);
                a[mt][0] = f2tf32(a[mt][0]); a[mt][1] = f2tf32(a[mt][1]);
                a[mt][2] = f2tf32(a[mt][2]); a[mt][3] = f2tf32(a[mt][3]);
            }
            #pragma unroll
            for (int p = 0; p < 4; p++) {
                uint32_t r0, r1, r2, r3;
                ldsm4(r0, r1, r2, r3, sB + p * 1024 + pc);
                b[2 * p][0]     = f2tf32(r0);
                b[2 * p + 1][0] = f2tf32(r1);
                b[2 * p][1]     = f2tf32(r2);
                b[2 * p + 1][1] = f2tf32(r3);
            }
            #pragma unroll
            for (int mt = 0; mt < 4; mt++)
                #pragma unroll
                for (int nt = 0; nt < 8; nt++)
                    mma_tf32(acc[mt][nt], a[mt], b[nt]);
        }
    }

    // ---- epilogue. Frag: c0,c1 -> row qr cols 2qc,2qc+1; c2,c3 -> row qr+8
    const int qr = lane >> 2, qc = lane & 3;
    #pragma unroll
    for (int mt = 0; mt < 4; mt++) {
        const int r0 = rowBase + wm * 64 + mt * 16 + qr;
        const int r1 = r0 + 8;
        if (MODE == 0) {
            #pragma unroll
            for (int nt = 0; nt < 8; nt++) {
                const int cg = colBase + wn * 64 + nt * 8 + 2 * qc;
                float t0 = fmaxf(acc[mt][nt][0], 0.f);
                float t1 = fmaxf(acc[mt][nt][1], 0.f);
                float t2 = fmaxf(acc[mt][nt][2], 0.f);
                float t3 = fmaxf(acc[mt][nt][3], 0.f);
                *(float2*)(g_H + (size_t)r0 * HDIM + cg) = make_float2(t0 * t0, t1 * t1);
                *(float2*)(g_H + (size_t)r1 * HDIM + cg) = make_float2(t2 * t2, t3 * t3);
            }
        } else {
            int   tok0 = g_rowTok[r0],  tok1 = g_rowTok[r1];
            float w0   = g_rowW[r0],    w1   = g_rowW[r1];
            int   sl0  = g_rowSlot[r0], sl1  = g_rowSlot[r1];
            #pragma unroll
            for (int nt = 0; nt < 8; nt++) {
                const int cg = colBase + wn * 64 + nt * 8 + 2 * qc;
                if (tok0 >= 0)
                    *(float2*)(g_ys + (size_t)sl0 * DIM + cg) =
                        make_float2(w0 * acc[mt][nt][0], w0 * acc[mt][nt][1]);
                if (tok1 >= 0)
                    *(float2*)(g_ys + (size_t)sl1 * DIM + cg) =
                        make_float2(w1 * acc[mt][nt][2], w1 * acc[mt][nt][3]);
            }
        }
    }
}

// ---------------- K6: combine two slots per token ---------------------------
__global__ void k_combine(float* __restrict__ out) {
    int i = blockIdx.x * blockDim.x + threadIdx.x;
    const int PR = DIM / 4;
    if (i >= N_TOK * PR) return;
    int n = i / PR;
    int c = i - n * PR;
    const float4* ys = (const float4*)g_ys;
    float4 a = ys[(size_t)(2 * n) * PR + c];
    float4 b = ys[(size_t)(2 * n + 1) * PR + c];
    float4 o;
    o.x = a.x + b.x; o.y = a.y + b.y; o.z = a.z + b.z; o.w = a.w + b.w;
    ((float4*)out)[(size_t)n * PR + c] = o;
}

// ---------------------------------------------------------------------------
extern "C" void kernel_launch(void* const* d_in, const int* in_sizes, int n_in,
                              void* d_out, int out_size) {
    const float* x   = (const float*)d_in[0];   // [8192, 1024]
    const float* gw  = (const float*)d_in[1];   // [8, 1024]
    const float* wfc = (const float*)d_in[2];   // [8, 4096, 1024]
    const float* wpj = (const float*)d_in[3];   // [8, 1024, 4096]
    float* out = (float*)d_out;

    const int SMEM_BYTES = NSTAGE * STAGE_BYTES;   // 65536
    cudaFuncSetAttribute(k_mma<DIM, 0>,  cudaFuncAttributeMaxDynamicSharedMemorySize, SMEM_BYTES);
    cudaFuncSetAttribute(k_mma<HDIM, 1>, cudaFuncAttributeMaxDynamicSharedMemorySize, SMEM_BYTES);

    k_init<<<CAP / 256, 256>>>();
    k_gate<<<N_TOK / 8, 256>>>(x, gw);
    k_scan<<<1, 32>>>(out, out_size);
    k_scatter<<<NSLOT / 256, 256>>>();

    dim3 g1(HDIM / 128, MAXTILES);              // 32 x 136
    k_mma<DIM, 0><<<g1, 128, SMEM_BYTES>>>(x, wfc);

    dim3 g2(DIM / 128, MAXTILES);               // 8 x 136
    k_mma<HDIM, 1><<<g2, 128, SMEM_BYTES>>>(nullptr, wpj);

    k_combine<<<(N_TOK * (DIM / 4) + 255) / 256, 256>>>(out);
}

// round 9
// speedup vs baseline: 3.1432x; 1.8985x over previous
#include <cuda_runtime.h>
#include <cuda_fp16.h>
#include <cstdint>
#include <math.h>

#define N_TOK 8192
#define DIM   1024
#define HDIM  4096
#define NEXP  8
#define NSLOT 16384
#define CAP   17408            // 16384 + 8*128 pad (per-expert pad to 128)
#define MAXTILES 136           // CAP / 128
#define STAGE_BYTES 16384      // (128 A rows + 128 B rows) * 64 B
#define NSTAGE 4

// ---------------- scratch (static __device__: no runtime alloc) ------------
__device__ __half g_Hh [(size_t)CAP   * HDIM];      // 142 MB relu^2 out, fp16
__device__ float  g_ys [(size_t)NSLOT * DIM];       // 64 MB per-slot weighted out
__device__ __half g_xh  [(size_t)N_TOK * DIM];      // 16 MB  x in fp16
__device__ __half g_wfch[(size_t)NEXP * HDIM * DIM]; // 64 MB w_fc fp16
__device__ __half g_wpjh[(size_t)NEXP * HDIM * DIM]; // 64 MB w_proj fp16
__device__ int   g_rowTok[CAP];
__device__ int   g_rowSlot[CAP];
__device__ float g_rowW[CAP];
__device__ int   g_slotE[NSLOT];
__device__ float g_slotW[NSLOT];
__device__ int   g_cnt[NEXP];
__device__ int   g_cursor[NEXP];
__device__ int   g_padOff[NEXP + 1];
__device__ int   g_tileE[MAXTILES];
__device__ float g_probSum[NEXP];

// ---------------- helpers ---------------------------------------------------
__device__ __forceinline__ uint32_t smem_to_u32(const void* p) {
    uint32_t a;
    asm("{ .reg .u64 t; cvta.to.shared.u64 t, %1; cvt.u32.u64 %0, t; }"
        : "=r"(a) : "l"(p));
    return a;
}
__device__ __forceinline__ void cpasync16(uint32_t s, const void* g) {
    asm volatile("cp.async.cg.shared.global [%0], [%1], 16;" :: "r"(s), "l"(g) : "memory");
}
__device__ __forceinline__ void ldsm4(uint32_t& r0, uint32_t& r1, uint32_t& r2,
                                      uint32_t& r3, uint32_t addr) {
    asm volatile("ldmatrix.sync.aligned.m8n8.x4.shared.b16 {%0,%1,%2,%3}, [%4];"
                 : "=r"(r0), "=r"(r1), "=r"(r2), "=r"(r3) : "r"(addr));
}
__device__ __forceinline__ void mma_f16(float* c, const uint32_t* a, const uint32_t* b) {
    asm volatile(
        "mma.sync.aligned.m16n8k16.row.col.f32.f16.f16.f32 "
        "{%0,%1,%2,%3}, {%4,%5,%6,%7}, {%8,%9}, {%0,%1,%2,%3};"
        : "+f"(c[0]), "+f"(c[1]), "+f"(c[2]), "+f"(c[3])
        : "r"(a[0]), "r"(a[1]), "r"(a[2]), "r"(a[3]), "r"(b[0]), "r"(b[1]));
}

// ---------------- K_half: fp32 -> fp16 bulk convert -------------------------
__global__ void k_half(const float4* __restrict__ in, uint2* __restrict__ out, int n4) {
    int i = blockIdx.x * blockDim.x + threadIdx.x;
    if (i >= n4) return;
    float4 v = in[i];
    __half2 h0 = __floats2half2_rn(v.x, v.y);
    __half2 h1 = __floats2half2_rn(v.z, v.w);
    out[i] = make_uint2(*(uint32_t*)&h0, *(uint32_t*)&h1);
}

// ---------------- K0: reset -------------------------------------------------
__global__ void k_init() {
    int i = blockIdx.x * blockDim.x + threadIdx.x;
    if (i < CAP) g_rowTok[i] = -1;
    if (i < NEXP) { g_cnt[i] = 0; g_cursor[i] = 0; g_probSum[i] = 0.f; }
}

// ---------------- K1: gating (exact fp32) ----------------------------------
__global__ __launch_bounds__(256) void k_gate(const float* __restrict__ x,
                                              const float* __restrict__ gw) {
    __shared__ float sProb[NEXP];
    __shared__ int   sCnt[NEXP];
    int tid = threadIdx.x;
    if (tid < NEXP) { sProb[tid] = 0.f; sCnt[tid] = 0; }
    __syncthreads();
    int warp = tid >> 5, lane = tid & 31;
    int n = blockIdx.x * 8 + warp;
    const float* xr = x + (size_t)n * DIM;
    float xv[32];
    #pragma unroll
    for (int j = 0; j < 32; j++) xv[j] = xr[j * 32 + lane];
    float logit[NEXP];
    #pragma unroll
    for (int e = 0; e < NEXP; e++) {
        const float* g = gw + e * DIM;
        float s = 0.f;
        #pragma unroll
        for (int j = 0; j < 32; j++) s += xv[j] * g[j * 32 + lane];
        #pragma unroll
        for (int o = 16; o; o >>= 1) s += __shfl_xor_sync(0xffffffffu, s, o);
        logit[e] = s;
    }
    if (lane == 0) {
        float m = logit[0];
        #pragma unroll
        for (int e = 1; e < NEXP; e++) m = fmaxf(m, logit[e]);
        float p[NEXP]; float Z = 0.f;
        #pragma unroll
        for (int e = 0; e < NEXP; e++) { p[e] = expf(logit[e] - m); Z += p[e]; }
        float inv = 1.f / Z;
        #pragma unroll
        for (int e = 0; e < NEXP; e++) p[e] *= inv;
        int i1 = 0;
        #pragma unroll
        for (int e = 1; e < NEXP; e++) if (p[e] > p[i1]) i1 = e;
        int i2 = (i1 == 0) ? 1 : 0;
        #pragma unroll
        for (int e = 0; e < NEXP; e++) if (e != i1 && p[e] > p[i2]) i2 = e;
        float s2 = p[i1] + p[i2];
        g_slotE[2 * n]     = i1;  g_slotW[2 * n]     = p[i1] / s2;
        g_slotE[2 * n + 1] = i2;  g_slotW[2 * n + 1] = p[i2] / s2;
        atomicAdd(&sCnt[i1], 1);
        atomicAdd(&sCnt[i2], 1);
        #pragma unroll
        for (int e = 0; e < NEXP; e++) atomicAdd(&sProb[e], p[e]);
    }
    __syncthreads();
    if (tid < NEXP) {
        atomicAdd(&g_probSum[tid], sProb[tid]);
        atomicAdd(&g_cnt[tid], sCnt[tid]);
    }
}

// ---------------- K2: scan + tile map + balance loss ------------------------
__global__ void k_scan(float* out, int out_size) {
    if (threadIdx.x != 0 || blockIdx.x != 0) return;
    int off = 0;
    for (int e = 0; e < NEXP; e++) {
        g_padOff[e] = off;
        off += ((g_cnt[e] + 127) >> 7) << 7;
    }
    g_padOff[NEXP] = off;
    for (int e = 0; e < NEXP; e++)
        for (int t = g_padOff[e] >> 7; t < (g_padOff[e + 1] >> 7); t++) g_tileE[t] = e;
    for (int t = off >> 7; t < MAXTILES; t++) g_tileE[t] = -1;
    if (out_size > N_TOK * DIM) {
        float l = 0.f;
        for (int e = 0; e < NEXP; e++) l += g_probSum[e] * (float)g_cnt[e];
        out[(size_t)N_TOK * DIM] = l * (float)NEXP / ((float)N_TOK * (float)N_TOK);
    }
}

// ---------------- K3: scatter -----------------------------------------------
__global__ void k_scatter() {
    int s = blockIdx.x * blockDim.x + threadIdx.x;
    if (s >= NSLOT) return;
    int e = g_slotE[s];
    int pos = g_padOff[e] + atomicAdd(&g_cursor[e], 1);
    g_rowTok[pos]  = s >> 1;
    g_rowSlot[pos] = s;
    g_rowW[pos]    = g_slotW[s];
}

// ---------------------------------------------------------------------------
// fp16 mma.sync m16n8k16 GEMM. CTA 128x128, 128 threads (2x2 warps of 64x64),
// K-stage 32 halves (64B rows), 4-stage cp.async pipeline, XOR-swizzled smem.
// MODE 0: A = g_xh rows gathered via g_rowTok, W = g_wfch[e], epi relu^2 -> g_Hh
// MODE 1: A = g_Hh rows (direct),              W = g_wpjh[e], epi *rowW  -> g_ys
// ---------------------------------------------------------------------------
template<int KD, int MODE>
__global__ void __launch_bounds__(128) k_mma(const __half* __restrict__ Ag,
                                             const __half* __restrict__ Wg) {
    int e = g_tileE[blockIdx.y];
    if (e < 0) return;
    extern __shared__ char smem[];   // NSTAGE * STAGE_BYTES
    const int tid = threadIdx.x;
    const int rowBase = blockIdx.y << 7;
    const int colBase = blockIdx.x << 7;

    // ---- loader mapping: thread t owns A row t and B row t (32 halves/stage)
    const __half* aSrc;
    if (MODE == 0) {
        int tok = g_rowTok[rowBase + tid];
        if (tok < 0) tok = 0;                       // pad rows: valid dummy data
        aSrc = Ag + (size_t)tok * KD;
    } else {
        aSrc = g_Hh + (size_t)(rowBase + tid) * KD;
    }
    const __half* bSrc = Wg + (size_t)e * ((size_t)HDIM * DIM)
                       + (size_t)(colBase + tid) * KD;

    const uint32_t sb = smem_to_u32(smem);
    const uint32_t wsw = (tid >> 1) & 3;            // writer swizzle
    uint32_t aOff[4];
    #pragma unroll
    for (int j = 0; j < 4; j++) aOff[j] = tid * 64 + ((j ^ wsw) << 4);

    const int T = KD / 32;

    // prologue: stages 0..NSTAGE-2
    #pragma unroll
    for (int t = 0; t < NSTAGE - 1; t++) {
        uint32_t so = sb + t * STAGE_BYTES;
        const __half* ga = aSrc + t * 32;
        const __half* gb = bSrc + t * 32;
        #pragma unroll
        for (int j = 0; j < 4; j++) {
            cpasync16(so + aOff[j], ga + j * 8);
            cpasync16(so + 8192 + aOff[j], gb + j * 8);
        }
        asm volatile("cp.async.commit_group;" ::: "memory");
    }

    // ---- compute mapping (ldmatrix lane geometry)
    const int wid = tid >> 5, lane = tid & 31;
    const int wm = wid >> 1, wn = wid & 1;          // 2x2 warps of 64x64
    const int mat = lane >> 3;
    const int l8  = ((mat & 1) << 3) + (lane & 7);  // row-within-16
    const int cm  = mat >> 1;                       // 16B chunk sub-index
    const int rsw = (l8 >> 1) & 3;                  // reader swizzle
    const uint32_t pc0 = (uint32_t)(((0 + cm) ^ rsw) << 4);  // kb=0
    const uint32_t pc1 = (uint32_t)(((2 + cm) ^ rsw) << 4);  // kb=1
    const uint32_t aLane = (uint32_t)(wm * 4096 + l8 * 64);
    const uint32_t bLane = (uint32_t)(8192 + wn * 4096 + l8 * 64);

    float acc[4][8][4];
    #pragma unroll
    for (int i = 0; i < 4; i++)
        #pragma unroll
        for (int j = 0; j < 8; j++)
            #pragma unroll
            for (int q = 0; q < 4; q++) acc[i][j][q] = 0.f;

    for (int jt = 0; jt < T; jt++) {
        if (jt < T - 2)       asm volatile("cp.async.wait_group 2;" ::: "memory");
        else if (jt == T - 2) asm volatile("cp.async.wait_group 1;" ::: "memory");
        else                  asm volatile("cp.async.wait_group 0;" ::: "memory");
        __syncthreads();

        if (jt + NSTAGE - 1 < T) {
            int t = jt + NSTAGE - 1;
            uint32_t so = sb + (t & (NSTAGE - 1)) * STAGE_BYTES;
            const __half* ga = aSrc + t * 32;
            const __half* gb = bSrc + t * 32;
            #pragma unroll
            for (int j = 0; j < 4; j++) {
                cpasync16(so + aOff[j], ga + j * 8);
                cpasync16(so + 8192 + aOff[j], gb + j * 8);
            }
            asm volatile("cp.async.commit_group;" ::: "memory");
        }

        const uint32_t so = sb + (jt & (NSTAGE - 1)) * STAGE_BYTES;
        const uint32_t sA = so + aLane;
        const uint32_t sB = so + bLane;

        #pragma unroll
        for (int kb = 0; kb < 2; kb++) {
            const uint32_t pc = kb ? pc1 : pc0;
            uint32_t a[4][4], b[8][2];
            #pragma unroll
            for (int mt = 0; mt < 4; mt++)
                ldsm4(a[mt][0], a[mt][1], a[mt][2], a[mt][3], sA + mt * 1024 + pc);
            #pragma unroll
            for (int p = 0; p < 4; p++) {
                uint32_t r0, r1, r2, r3;
                ldsm4(r0, r1, r2, r3, sB + p * 1024 + pc);
                b[2 * p][0]     = r0;
                b[2 * p + 1][0] = r1;
                b[2 * p][1]     = r2;
                b[2 * p + 1][1] = r3;
            }
            #pragma unroll
            for (int mt = 0; mt < 4; mt++)
                #pragma unroll
                for (int nt = 0; nt < 8; nt++)
                    mma_f16(acc[mt][nt], a[mt], b[nt]);
        }
    }

    // ---- epilogue. Frag: c0,c1 -> row qr cols 2qc,2qc+1; c2,c3 -> row qr+8
    const int qr = lane >> 2, qc = lane & 3;
    #pragma unroll
    for (int mt = 0; mt < 4; mt++) {
        const int r0 = rowBase + wm * 64 + mt * 16 + qr;
        const int r1 = r0 + 8;
        if (MODE == 0) {
            #pragma unroll
            for (int nt = 0; nt < 8; nt++) {
                const int cg = colBase + wn * 64 + nt * 8 + 2 * qc;
                float t0 = fmaxf(acc[mt][nt][0], 0.f);
                float t1 = fmaxf(acc[mt][nt][1], 0.f);
                float t2 = fmaxf(acc[mt][nt][2], 0.f);
                float t3 = fmaxf(acc[mt][nt][3], 0.f);
                *(__half2*)(g_Hh + (size_t)r0 * HDIM + cg) = __floats2half2_rn(t0 * t0, t1 * t1);
                *(__half2*)(g_Hh + (size_t)r1 * HDIM + cg) = __floats2half2_rn(t2 * t2, t3 * t3);
            }
        } else {
            int   tok0 = g_rowTok[r0],  tok1 = g_rowTok[r1];
            float w0   = g_rowW[r0],    w1   = g_rowW[r1];
            int   sl0  = g_rowSlot[r0], sl1  = g_rowSlot[r1];
            #pragma unroll
            for (int nt = 0; nt < 8; nt++) {
                const int cg = colBase + wn * 64 + nt * 8 + 2 * qc;
                if (tok0 >= 0)
                    *(float2*)(g_ys + (size_t)sl0 * DIM + cg) =
                        make_float2(w0 * acc[mt][nt][0], w0 * acc[mt][nt][1]);
                if (tok1 >= 0)
                    *(float2*)(g_ys + (size_t)sl1 * DIM + cg) =
                        make_float2(w1 * acc[mt][nt][2], w1 * acc[mt][nt][3]);
            }
        }
    }
}

// ---------------- K6: combine two slots per token ---------------------------
__global__ void k_combine(float* __restrict__ out) {
    int i = blockIdx.x * blockDim.x + threadIdx.x;
    const int PR = DIM / 4;
    if (i >= N_TOK * PR) return;
    int n = i / PR;
    int c = i - n * PR;
    const float4* ys = (const float4*)g_ys;
    float4 a = ys[(size_t)(2 * n) * PR + c];
    float4 b = ys[(size_t)(2 * n + 1) * PR + c];
    float4 o;
    o.x = a.x + b.x; o.y = a.y + b.y; o.z = a.z + b.z; o.w = a.w + b.w;
    ((float4*)out)[(size_t)n * PR + c] = o;
}

// ---------------------------------------------------------------------------
extern "C" void kernel_launch(void* const* d_in, const int* in_sizes, int n_in,
                              void* d_out, int out_size) {
    const float* x   = (const float*)d_in[0];   // [8192, 1024]
    const float* gw  = (const float*)d_in[1];   // [8, 1024]
    const float* wfc = (const float*)d_in[2];   // [8, 4096, 1024]
    const float* wpj = (const float*)d_in[3];   // [8, 1024, 4096]
    float* out = (float*)d_out;

    const int SMEM_BYTES = NSTAGE * STAGE_BYTES;   // 65536
    cudaFuncSetAttribute(k_mma<DIM, 0>,  cudaFuncAttributeMaxDynamicSharedMemorySize, SMEM_BYTES);
    cudaFuncSetAttribute(k_mma<HDIM, 1>, cudaFuncAttributeMaxDynamicSharedMemorySize, SMEM_BYTES);

    // fp32 -> fp16 conversions
    __half *xh, *wfh, *wph;
    cudaGetSymbolAddress((void**)&xh,  g_xh);
    cudaGetSymbolAddress((void**)&wfh, g_wfch);
    cudaGetSymbolAddress((void**)&wph, g_wpjh);
    {
        int n4 = N_TOK * DIM / 4;
        k_half<<<(n4 + 255) / 256, 256>>>((const float4*)x, (uint2*)xh, n4);
        n4 = NEXP * HDIM * DIM / 4;
        k_half<<<(n4 + 255) / 256, 256>>>((const float4*)wfc, (uint2*)wfh, n4);
        k_half<<<(n4 + 255) / 256, 256>>>((const float4*)wpj, (uint2*)wph, n4);
    }

    k_init<<<CAP / 256, 256>>>();
    k_gate<<<N_TOK / 8, 256>>>(x, gw);
    k_scan<<<1, 32>>>(out, out_size);
    k_scatter<<<NSLOT / 256, 256>>>();

    dim3 g1(HDIM / 128, MAXTILES);              // 32 x 136
    k_mma<DIM, 0><<<g1, 128, SMEM_BYTES>>>(xh, wfh);

    dim3 g2(DIM / 128, MAXTILES);               // 8 x 136
    k_mma<HDIM, 1><<<g2, 128, SMEM_BYTES>>>(nullptr, wph);

    k_combine<<<(N_TOK * (DIM / 4) + 255) / 256, 256>>>(out);
}

// round 10
// speedup vs baseline: 3.4109x; 1.0852x over previous
#include <cuda_runtime.h>
#include <cuda_fp16.h>
#include <cstdint>
#include <math.h>

#define N_TOK 8192
#define DIM   1024
#define HDIM  4096
#define NEXP  8
#define NSLOT 16384
#define CAP   17408            // 16384 + 8*128 pad (per-expert pad to 128)
#define MAXTILES 136           // CAP / 128
#define BN    256              // CTA cols
#define KSTG  64               // K halves per stage (128B rows)
#define STAGE_BYTES ((128 + BN) * 128)   // A 16KB + B 32KB = 49152
#define NSTAGE 4

// ---------------- scratch (static __device__: no runtime alloc) ------------
__device__ __half g_Hh [(size_t)CAP   * HDIM];       // 142 MB relu^2 out, fp16
__device__ float  g_ys [(size_t)NSLOT * DIM];        // 64 MB per-slot weighted out
__device__ __half g_xh  [(size_t)N_TOK * DIM];       // 16 MB  x in fp16
__device__ __half g_wfch[(size_t)NEXP * HDIM * DIM]; // 64 MB w_fc fp16
__device__ __half g_wpjh[(size_t)NEXP * HDIM * DIM]; // 64 MB w_proj fp16
__device__ int   g_rowTok[CAP];
__device__ int   g_rowSlot[CAP];
__device__ float g_rowW[CAP];
__device__ int   g_slotE[NSLOT];
__device__ float g_slotW[NSLOT];
__device__ int   g_cnt[NEXP];
__device__ int   g_cursor[NEXP];
__device__ int   g_padOff[NEXP + 1];
__device__ int   g_tileE[MAXTILES];
__device__ float g_probSum[NEXP];

// ---------------- helpers ---------------------------------------------------
__device__ __forceinline__ uint32_t smem_to_u32(const void* p) {
    uint32_t a;
    asm("{ .reg .u64 t; cvta.to.shared.u64 t, %1; cvt.u32.u64 %0, t; }"
        : "=r"(a) : "l"(p));
    return a;
}
__device__ __forceinline__ void cpasync16(uint32_t s, const void* g) {
    asm volatile("cp.async.cg.shared.global [%0], [%1], 16;" :: "r"(s), "l"(g) : "memory");
}
__device__ __forceinline__ void ldsm4(uint32_t& r0, uint32_t& r1, uint32_t& r2,
                                      uint32_t& r3, uint32_t addr) {
    asm volatile("ldmatrix.sync.aligned.m8n8.x4.shared.b16 {%0,%1,%2,%3}, [%4];"
                 : "=r"(r0), "=r"(r1), "=r"(r2), "=r"(r3) : "r"(addr));
}
__device__ __forceinline__ void mma_f16(float* c, const uint32_t* a, const uint32_t* b) {
    asm volatile(
        "mma.sync.aligned.m16n8k16.row.col.f32.f16.f16.f32 "
        "{%0,%1,%2,%3}, {%4,%5,%6,%7}, {%8,%9}, {%0,%1,%2,%3};"
        : "+f"(c[0]), "+f"(c[1]), "+f"(c[2]), "+f"(c[3])
        : "r"(a[0]), "r"(a[1]), "r"(a[2]), "r"(a[3]), "r"(b[0]), "r"(b[1]));
}

// ---------------- K_half: fp32 -> fp16 bulk convert -------------------------
__global__ void k_half(const float4* __restrict__ in, uint2* __restrict__ out, int n4) {
    int i = blockIdx.x * blockDim.x + threadIdx.x;
    if (i >= n4) return;
    float4 v = in[i];
    __half2 h0 = __floats2half2_rn(v.x, v.y);
    __half2 h1 = __floats2half2_rn(v.z, v.w);
    out[i] = make_uint2(*(uint32_t*)&h0, *(uint32_t*)&h1);
}

// ---------------- K0: reset -------------------------------------------------
__global__ void k_init() {
    int i = blockIdx.x * blockDim.x + threadIdx.x;
    if (i < CAP) g_rowTok[i] = -1;
    if (i < NEXP) { g_cnt[i] = 0; g_cursor[i] = 0; g_probSum[i] = 0.f; }
}

// ---------------- K1: gating (exact fp32) ----------------------------------
__global__ __launch_bounds__(256) void k_gate(const float* __restrict__ x,
                                              const float* __restrict__ gw) {
    __shared__ float sProb[NEXP];
    __shared__ int   sCnt[NEXP];
    int tid = threadIdx.x;
    if (tid < NEXP) { sProb[tid] = 0.f; sCnt[tid] = 0; }
    __syncthreads();
    int warp = tid >> 5, lane = tid & 31;
    int n = blockIdx.x * 8 + warp;
    const float* xr = x + (size_t)n * DIM;
    float xv[32];
    #pragma unroll
    for (int j = 0; j < 32; j++) xv[j] = xr[j * 32 + lane];
    float logit[NEXP];
    #pragma unroll
    for (int e = 0; e < NEXP; e++) {
        const float* g = gw + e * DIM;
        float s = 0.f;
        #pragma unroll
        for (int j = 0; j < 32; j++) s += xv[j] * g[j * 32 + lane];
        #pragma unroll
        for (int o = 16; o; o >>= 1) s += __shfl_xor_sync(0xffffffffu, s, o);
        logit[e] = s;
    }
    if (lane == 0) {
        float m = logit[0];
        #pragma unroll
        for (int e = 1; e < NEXP; e++) m = fmaxf(m, logit[e]);
        float p[NEXP]; float Z = 0.f;
        #pragma unroll
        for (int e = 0; e < NEXP; e++) { p[e] = expf(logit[e] - m); Z += p[e]; }
        float inv = 1.f / Z;
        #pragma unroll
        for (int e = 0; e < NEXP; e++) p[e] *= inv;
        int i1 = 0;
        #pragma unroll
        for (int e = 1; e < NEXP; e++) if (p[e] > p[i1]) i1 = e;
        int i2 = (i1 == 0) ? 1 : 0;
        #pragma unroll
        for (int e = 0; e < NEXP; e++) if (e != i1 && p[e] > p[i2]) i2 = e;
        float s2 = p[i1] + p[i2];
        g_slotE[2 * n]     = i1;  g_slotW[2 * n]     = p[i1] / s2;
        g_slotE[2 * n + 1] = i2;  g_slotW[2 * n + 1] = p[i2] / s2;
        atomicAdd(&sCnt[i1], 1);
        atomicAdd(&sCnt[i2], 1);
        #pragma unroll
        for (int e = 0; e < NEXP; e++) atomicAdd(&sProb[e], p[e]);
    }
    __syncthreads();
    if (tid < NEXP) {
        atomicAdd(&g_probSum[tid], sProb[tid]);
        atomicAdd(&g_cnt[tid], sCnt[tid]);
    }
}

// ---------------- K2: scan + tile map + balance loss ------------------------
__global__ void k_scan(float* out, int out_size) {
    if (threadIdx.x != 0 || blockIdx.x != 0) return;
    int off = 0;
    for (int e = 0; e < NEXP; e++) {
        g_padOff[e] = off;
        off += ((g_cnt[e] + 127) >> 7) << 7;
    }
    g_padOff[NEXP] = off;
    for (int e = 0; e < NEXP; e++)
        for (int t = g_padOff[e] >> 7; t < (g_padOff[e + 1] >> 7); t++) g_tileE[t] = e;
    for (int t = off >> 7; t < MAXTILES; t++) g_tileE[t] = -1;
    if (out_size > N_TOK * DIM) {
        float l = 0.f;
        for (int e = 0; e < NEXP; e++) l += g_probSum[e] * (float)g_cnt[e];
        out[(size_t)N_TOK * DIM] = l * (float)NEXP / ((float)N_TOK * (float)N_TOK);
    }
}

// ---------------- K3: scatter -----------------------------------------------
__global__ void k_scatter() {
    int s = blockIdx.x * blockDim.x + threadIdx.x;
    if (s >= NSLOT) return;
    int e = g_slotE[s];
    int pos = g_padOff[e] + atomicAdd(&g_cursor[e], 1);
    g_rowTok[pos]  = s >> 1;
    g_rowSlot[pos] = s;
    g_rowW[pos]    = g_slotW[s];
}

// ---------------------------------------------------------------------------
// fp16 mma.sync m16n8k16 GEMM. CTA 128x256, 256 threads (2x4 warps of 64x64),
// K-stage 64 halves (128B rows, 8 chunks), 4-stage cp.async pipeline.
// Swizzle: phys_chunk = chunk ^ (row & 7)  (conflict-free writers + ldsm).
// MODE 0: A = g_xh rows gathered via g_rowTok, W = g_wfch[e], epi relu^2 -> g_Hh
// MODE 1: A = g_Hh rows (direct),              W = g_wpjh[e], epi *rowW  -> g_ys
// ---------------------------------------------------------------------------
template<int KD, int MODE>
__global__ void __launch_bounds__(256) k_mma(const __half* __restrict__ Ag,
                                             const __half* __restrict__ Wg) {
    int e = g_tileE[blockIdx.y];
    if (e < 0) return;
    extern __shared__ char smem[];   // NSTAGE * STAGE_BYTES
    const int tid = threadIdx.x;
    const int rowBase = blockIdx.y << 7;
    const int colBase = blockIdx.x * BN;

    // ---- loader mapping:
    //   A: thread t loads row t>>1, chunks (t&1)*4 .. +3   (4 x cp.async)
    //   B: thread t loads row t, chunks 0..7               (8 x cp.async)
    const __half* aSrc;
    {
        int ar = rowBase + (tid >> 1);
        if (MODE == 0) {
            int tok = g_rowTok[ar];
            if (tok < 0) tok = 0;                   // pad rows: valid dummy data
            aSrc = Ag + (size_t)tok * KD;
        } else {
            aSrc = g_Hh + (size_t)ar * KD;
        }
    }
    const __half* bSrc = Wg + (size_t)e * ((size_t)HDIM * DIM)
                       + (size_t)(colBase + tid) * KD;

    const uint32_t sb = smem_to_u32(smem);
    const int aj0 = (tid & 1) * 4;                  // A chunk base
    uint32_t aOff[4], bOff[8];
    #pragma unroll
    for (int j = 0; j < 4; j++)
        aOff[j] = (tid >> 1) * 128 + (((aj0 + j) ^ ((tid >> 1) & 7)) << 4);
    #pragma unroll
    for (int j = 0; j < 8; j++)
        bOff[j] = 16384 + tid * 128 + ((j ^ (tid & 7)) << 4);

    const int T = KD / KSTG;

    // prologue: stages 0..NSTAGE-2
    #pragma unroll
    for (int t = 0; t < NSTAGE - 1; t++) {
        uint32_t so = sb + t * STAGE_BYTES;
        const __half* ga = aSrc + t * KSTG;
        const __half* gb = bSrc + t * KSTG;
        #pragma unroll
        for (int j = 0; j < 4; j++) cpasync16(so + aOff[j], ga + (aj0 + j) * 8);
        #pragma unroll
        for (int j = 0; j < 8; j++) cpasync16(so + bOff[j], gb + j * 8);
        asm volatile("cp.async.commit_group;" ::: "memory");
    }

    // ---- compute mapping (ldmatrix lane geometry)
    const int wid = tid >> 5, lane = tid & 31;
    const int wm = wid >> 2, wn = wid & 3;          // 2x4 warps of 64x64
    const int mat = lane >> 3;
    const int l8  = ((mat & 1) << 3) + (lane & 7);  // row-within-16
    const int cm  = mat >> 1;                       // 16B chunk sub-index
    const int rsw = l8 & 7;                         // reader swizzle
    uint32_t pc[4];
    #pragma unroll
    for (int kb = 0; kb < 4; kb++) pc[kb] = (uint32_t)(((2 * kb + cm) ^ rsw) << 4);
    const uint32_t aLane = (uint32_t)(wm * 8192 + l8 * 128);
    const uint32_t bLane = (uint32_t)(16384 + wn * 8192 + l8 * 128);

    float acc[4][8][4];
    #pragma unroll
    for (int i = 0; i < 4; i++)
        #pragma unroll
        for (int j = 0; j < 8; j++)
            #pragma unroll
            for (int q = 0; q < 4; q++) acc[i][j][q] = 0.f;

    for (int jt = 0; jt < T; jt++) {
        if (jt < T - 2)       asm volatile("cp.async.wait_group 2;" ::: "memory");
        else if (jt == T - 2) asm volatile("cp.async.wait_group 1;" ::: "memory");
        else                  asm volatile("cp.async.wait_group 0;" ::: "memory");
        __syncthreads();

        if (jt + NSTAGE - 1 < T) {
            int t = jt + NSTAGE - 1;
            uint32_t so = sb + (t & (NSTAGE - 1)) * STAGE_BYTES;
            const __half* ga = aSrc + t * KSTG;
            const __half* gb = bSrc + t * KSTG;
            #pragma unroll
            for (int j = 0; j < 4; j++) cpasync16(so + aOff[j], ga + (aj0 + j) * 8);
            #pragma unroll
            for (int j = 0; j < 8; j++) cpasync16(so + bOff[j], gb + j * 8);
            asm volatile("cp.async.commit_group;" ::: "memory");
        }

        const uint32_t so = sb + (jt & (NSTAGE - 1)) * STAGE_BYTES;
        const uint32_t sA = so + aLane;
        const uint32_t sB = so + bLane;

        #pragma unroll
        for (int kb = 0; kb < 4; kb++) {
            const uint32_t c = pc[kb];
            uint32_t a[4][4], b[8][2];
            #pragma unroll
            for (int mt = 0; mt < 4; mt++)
                ldsm4(a[mt][0], a[mt][1], a[mt][2], a[mt][3], sA + mt * 2048 + c);
            #pragma unroll
            for (int p = 0; p < 4; p++) {
                uint32_t r0, r1, r2, r3;
                ldsm4(r0, r1, r2, r3, sB + p * 2048 + c);
                b[2 * p][0]     = r0;
                b[2 * p + 1][0] = r1;
                b[2 * p][1]     = r2;
                b[2 * p + 1][1] = r3;
            }
            #pragma unroll
            for (int mt = 0; mt < 4; mt++)
                #pragma unroll
                for (int nt = 0; nt < 8; nt++)
                    mma_f16(acc[mt][nt], a[mt], b[nt]);
        }
    }

    // ---- epilogue. Frag: c0,c1 -> row qr cols 2qc,2qc+1; c2,c3 -> row qr+8
    const int qr = lane >> 2, qc = lane & 3;
    #pragma unroll
    for (int mt = 0; mt < 4; mt++) {
        const int r0 = rowBase + wm * 64 + mt * 16 + qr;
        const int r1 = r0 + 8;
        if (MODE == 0) {
            #pragma unroll
            for (int nt = 0; nt < 8; nt++) {
                const int cg = colBase + wn * 64 + nt * 8 + 2 * qc;
                float t0 = fmaxf(acc[mt][nt][0], 0.f);
                float t1 = fmaxf(acc[mt][nt][1], 0.f);
                float t2 = fmaxf(acc[mt][nt][2], 0.f);
                float t3 = fmaxf(acc[mt][nt][3], 0.f);
                *(__half2*)(g_Hh + (size_t)r0 * HDIM + cg) = __floats2half2_rn(t0 * t0, t1 * t1);
                *(__half2*)(g_Hh + (size_t)r1 * HDIM + cg) = __floats2half2_rn(t2 * t2, t3 * t3);
            }
        } else {
            int   tok0 = g_rowTok[r0],  tok1 = g_rowTok[r1];
            float w0   = g_rowW[r0],    w1   = g_rowW[r1];
            int   sl0  = g_rowSlot[r0], sl1  = g_rowSlot[r1];
            #pragma unroll
            for (int nt = 0; nt < 8; nt++) {
                const int cg = colBase + wn * 64 + nt * 8 + 2 * qc;
                if (tok0 >= 0)
                    *(float2*)(g_ys + (size_t)sl0 * DIM + cg) =
                        make_float2(w0 * acc[mt][nt][0], w0 * acc[mt][nt][1]);
                if (tok1 >= 0)
                    *(float2*)(g_ys + (size_t)sl1 * DIM + cg) =
                        make_float2(w1 * acc[mt][nt][2], w1 * acc[mt][nt][3]);
            }
        }
    }
}

// ---------------- K6: combine two slots per token ---------------------------
__global__ void k_combine(float* __restrict__ out) {
    int i = blockIdx.x * blockDim.x + threadIdx.x;
    const int PR = DIM / 4;
    if (i >= N_TOK * PR) return;
    int n = i / PR;
    int c = i - n * PR;
    const float4* ys = (const float4*)g_ys;
    float4 a = ys[(size_t)(2 * n) * PR + c];
    float4 b = ys[(size_t)(2 * n + 1) * PR + c];
    float4 o;
    o.x = a.x + b.x; o.y = a.y + b.y; o.z = a.z + b.z; o.w = a.w + b.w;
    ((float4*)out)[(size_t)n * PR + c] = o;
}

// ---------------------------------------------------------------------------
extern "C" void kernel_launch(void* const* d_in, const int* in_sizes, int n_in,
                              void* d_out, int out_size) {
    const float* x   = (const float*)d_in[0];   // [8192, 1024]
    const float* gw  = (const float*)d_in[1];   // [8, 1024]
    const float* wfc = (const float*)d_in[2];   // [8, 4096, 1024]
    const float* wpj = (const float*)d_in[3];   // [8, 1024, 4096]
    float* out = (float*)d_out;

    const int SMEM_BYTES = NSTAGE * STAGE_BYTES;   // 196608
    cudaFuncSetAttribute(k_mma<DIM, 0>,  cudaFuncAttributeMaxDynamicSharedMemorySize, SMEM_BYTES);
    cudaFuncSetAttribute(k_mma<HDIM, 1>, cudaFuncAttributeMaxDynamicSharedMemorySize, SMEM_BYTES);

    // fp32 -> fp16 conversions
    __half *xh, *wfh, *wph;
    cudaGetSymbolAddress((void**)&xh,  g_xh);
    cudaGetSymbolAddress((void**)&wfh, g_wfch);
    cudaGetSymbolAddress((void**)&wph, g_wpjh);
    {
        int n4 = N_TOK * DIM / 4;
        k_half<<<(n4 + 255) / 256, 256>>>((const float4*)x, (uint2*)xh, n4);
        n4 = NEXP * HDIM * DIM / 4;
        k_half<<<(n4 + 255) / 256, 256>>>((const float4*)wfc, (uint2*)wfh, n4);
        k_half<<<(n4 + 255) / 256, 256>>>((const float4*)wpj, (uint2*)wph, n4);
    }

    k_init<<<CAP / 256, 256>>>();
    k_gate<<<N_TOK / 8, 256>>>(x, gw);
    k_scan<<<1, 32>>>(out, out_size);
    k_scatter<<<NSLOT / 256, 256>>>();

    dim3 g1(HDIM / BN, MAXTILES);               // 16 x 136
    k_mma<DIM, 0><<<g1, 256, SMEM_BYTES>>>(xh, wfh);

    dim3 g2(DIM / BN, MAXTILES);                // 4 x 136
    k_mma<HDIM, 1><<<g2, 256, SMEM_BYTES>>>(nullptr, wph);

    k_combine<<<(N_TOK * (DIM / 4) + 255) / 256, 256>>>(out);
}

// round 13
// speedup vs baseline: 4.5035x; 1.3204x over previous
#include <cuda_runtime.h>
#include <cuda_fp16.h>
#include <cstdint>
#include <math.h>

#define N_TOK 8192
#define DIM   1024
#define HDIM  4096
#define NEXP  8
#define NSLOT 16384
#define CAP   17408            // 16384 + 8*128 pad (per-expert pad to 128)
#define MAXTILES 136           // CAP / 128
#define BN    256              // CTA cols
#define KSTG  64               // K halves per stage (128B rows)
#define STAGE_BYTES ((128 + BN) * 128)   // A 16KB + B 32KB = 49152
#define NSTAGE 4
#define NTHR  512

// ---------------- scratch (static __device__: no runtime alloc) ------------
__device__ __half g_Hh [(size_t)CAP   * HDIM];       // 142 MB relu^2 out, fp16
__device__ float  g_ys [(size_t)NSLOT * DIM];        // 64 MB per-slot weighted out
__device__ __half g_xh  [(size_t)N_TOK * DIM];       // 16 MB  x in fp16
__device__ __half g_wfch[(size_t)NEXP * HDIM * DIM]; // 64 MB w_fc fp16
__device__ __half g_wpjh[(size_t)NEXP * HDIM * DIM]; // 64 MB w_proj fp16
__device__ int   g_rowTok[CAP];
__device__ int   g_rowSlot[CAP];
__device__ float g_rowW[CAP];
__device__ int   g_slotE[NSLOT];
__device__ float g_slotW[NSLOT];
__device__ int   g_cnt[NEXP];
__device__ int   g_cursor[NEXP];
__device__ int   g_padOff[NEXP + 1];
__device__ int   g_tileE[MAXTILES];
__device__ float g_probSum[NEXP];

// ---------------- helpers ---------------------------------------------------
__device__ __forceinline__ uint32_t smem_to_u32(const void* p) {
    uint32_t a;
    asm("{ .reg .u64 t; cvta.to.shared.u64 t, %1; cvt.u32.u64 %0, t; }"
        : "=r"(a) : "l"(p));
    return a;
}
__device__ __forceinline__ void cpasync16(uint32_t s, const void* g) {
    asm volatile("cp.async.cg.shared.global [%0], [%1], 16;" :: "r"(s), "l"(g) : "memory");
}
__device__ __forceinline__ void ldsm4(uint32_t& r0, uint32_t& r1, uint32_t& r2,
                                      uint32_t& r3, uint32_t addr) {
    asm volatile("ldmatrix.sync.aligned.m8n8.x4.shared.b16 {%0,%1,%2,%3}, [%4];"
                 : "=r"(r0), "=r"(r1), "=r"(r2), "=r"(r3) : "r"(addr));
}
__device__ __forceinline__ void mma_f16(float* c, const uint32_t* a, const uint32_t* b) {
    asm volatile(
        "mma.sync.aligned.m16n8k16.row.col.f32.f16.f16.f32 "
        "{%0,%1,%2,%3}, {%4,%5,%6,%7}, {%8,%9}, {%0,%1,%2,%3};"
        : "+f"(c[0]), "+f"(c[1]), "+f"(c[2]), "+f"(c[3])
        : "r"(a[0]), "r"(a[1]), "r"(a[2]), "r"(a[3]), "r"(b[0]), "r"(b[1]));
}

// ---------------- K_half: fp32 -> fp16 bulk convert -------------------------
__global__ void k_half(const float4* __restrict__ in, uint2* __restrict__ out, int n4) {
    int i = blockIdx.x * blockDim.x + threadIdx.x;
    if (i >= n4) return;
    float4 v = in[i];
    __half2 h0 = __floats2half2_rn(v.x, v.y);
    __half2 h1 = __floats2half2_rn(v.z, v.w);
    out[i] = make_uint2(*(uint32_t*)&h0, *(uint32_t*)&h1);
}

// ---------------- K0: reset -------------------------------------------------
__global__ void k_init() {
    int i = blockIdx.x * blockDim.x + threadIdx.x;
    if (i < CAP) g_rowTok[i] = -1;
    if (i < NEXP) { g_cnt[i] = 0; g_cursor[i] = 0; g_probSum[i] = 0.f; }
}

// ---------------- K1: gating (exact fp32) ----------------------------------
__global__ __launch_bounds__(256) void k_gate(const float* __restrict__ x,
                                              const float* __restrict__ gw) {
    __shared__ float sProb[NEXP];
    __shared__ int   sCnt[NEXP];
    int tid = threadIdx.x;
    if (tid < NEXP) { sProb[tid] = 0.f; sCnt[tid] = 0; }
    __syncthreads();
    int warp = tid >> 5, lane = tid & 31;
    int n = blockIdx.x * 8 + warp;
    const float* xr = x + (size_t)n * DIM;
    float xv[32];
    #pragma unroll
    for (int j = 0; j < 32; j++) xv[j] = xr[j * 32 + lane];
    float logit[NEXP];
    #pragma unroll
    for (int e = 0; e < NEXP; e++) {
        const float* g = gw + e * DIM;
        float s = 0.f;
        #pragma unroll
        for (int j = 0; j < 32; j++) s += xv[j] * g[j * 32 + lane];
        #pragma unroll
        for (int o = 16; o; o >>= 1) s += __shfl_xor_sync(0xffffffffu, s, o);
        logit[e] = s;
    }
    if (lane == 0) {
        float m = logit[0];
        #pragma unroll
        for (int e = 1; e < NEXP; e++) m = fmaxf(m, logit[e]);
        float p[NEXP]; float Z = 0.f;
        #pragma unroll
        for (int e = 0; e < NEXP; e++) { p[e] = expf(logit[e] - m); Z += p[e]; }
        float inv = 1.f / Z;
        #pragma unroll
        for (int e = 0; e < NEXP; e++) p[e] *= inv;
        int i1 = 0;
        #pragma unroll
        for (int e = 1; e < NEXP; e++) if (p[e] > p[i1]) i1 = e;
        int i2 = (i1 == 0) ? 1 : 0;
        #pragma unroll
        for (int e = 0; e < NEXP; e++) if (e != i1 && p[e] > p[i2]) i2 = e;
        float s2 = p[i1] + p[i2];
        g_slotE[2 * n]     = i1;  g_slotW[2 * n]     = p[i1] / s2;
        g_slotE[2 * n + 1] = i2;  g_slotW[2 * n + 1] = p[i2] / s2;
        atomicAdd(&sCnt[i1], 1);
        atomicAdd(&sCnt[i2], 1);
        #pragma unroll
        for (int e = 0; e < NEXP; e++) atomicAdd(&sProb[e], p[e]);
    }
    __syncthreads();
    if (tid < NEXP) {
        atomicAdd(&g_probSum[tid], sProb[tid]);
        atomicAdd(&g_cnt[tid], sCnt[tid]);
    }
}

// ---------------- K2: scan + tile map + balance loss ------------------------
__global__ void k_scan(float* out, int out_size) {
    if (threadIdx.x != 0 || blockIdx.x != 0) return;
    int off = 0;
    for (int e = 0; e < NEXP; e++) {
        g_padOff[e] = off;
        off += ((g_cnt[e] + 127) >> 7) << 7;
    }
    g_padOff[NEXP] = off;
    for (int e = 0; e < NEXP; e++)
        for (int t = g_padOff[e] >> 7; t < (g_padOff[e + 1] >> 7); t++) g_tileE[t] = e;
    for (int t = off >> 7; t < MAXTILES; t++) g_tileE[t] = -1;
    if (out_size > N_TOK * DIM) {
        float l = 0.f;
        for (int e = 0; e < NEXP; e++) l += g_probSum[e] * (float)g_cnt[e];
        out[(size_t)N_TOK * DIM] = l * (float)NEXP / ((float)N_TOK * (float)N_TOK);
    }
}

// ---------------- K3: scatter -----------------------------------------------
__global__ void k_scatter() {
    int s = blockIdx.x * blockDim.x + threadIdx.x;
    if (s >= NSLOT) return;
    int e = g_slotE[s];
    int pos = g_padOff[e] + atomicAdd(&g_cursor[e], 1);
    g_rowTok[pos]  = s >> 1;
    g_rowSlot[pos] = s;
    g_rowW[pos]    = g_slotW[s];
}

// ---------------------------------------------------------------------------
// fp16 mma.sync m16n8k16 GEMM. CTA 128x256, 512 threads (4x4 warps of 32x64),
// K-stage 64 halves (128B rows, 8 chunks), 4-stage cp.async pipeline.
// Swizzle: phys_chunk = chunk ^ (row & 7)  (conflict-free writers + ldsm).
// 16 warps -> 4 eligible warps/SMSP: latency & barrier bubbles covered.
// MODE 0: A = g_xh rows gathered via g_rowTok, W = g_wfch[e], epi relu^2 -> g_Hh
// MODE 1: A = g_Hh rows (direct),              W = g_wpjh[e], epi *rowW  -> g_ys
// ---------------------------------------------------------------------------
template<int KD, int MODE>
__global__ void __launch_bounds__(NTHR, 1) k_mma(const __half* __restrict__ Ag,
                                                 const __half* __restrict__ Wg) {
    int e = g_tileE[blockIdx.y];
    if (e < 0) return;
    extern __shared__ char smem[];   // NSTAGE * STAGE_BYTES
    const int tid = threadIdx.x;
    const int rowBase = blockIdx.y << 7;
    const int colBase = blockIdx.x * BN;

    // ---- loader mapping:
    //   A: thread t -> row t>>2, chunks (t&3)*2 .. +1   (2 x cp.async)
    //   B: thread t -> row t>>1, chunks (t&1)*4 .. +3   (4 x cp.async)
    const __half* aSrc;
    {
        int ar = rowBase + (tid >> 2);
        if (MODE == 0) {
            int tok = g_rowTok[ar];
            if (tok < 0) tok = 0;                   // pad rows: valid dummy data
            aSrc = Ag + (size_t)tok * KD;
        } else {
            aSrc = g_Hh + (size_t)ar * KD;
        }
    }
    const __half* bSrc = Wg + (size_t)e * ((size_t)HDIM * DIM)
                       + (size_t)(colBase + (tid >> 1)) * KD;

    const uint32_t sb = smem_to_u32(smem);
    const int acb = (tid & 3) * 2;                  // A chunk base
    const int bcb = (tid & 1) * 4;                  // B chunk base
    uint32_t aOff[2], bOff[4];
    #pragma unroll
    for (int j = 0; j < 2; j++)
        aOff[j] = (tid >> 2) * 128 + (((acb + j) ^ ((tid >> 2) & 7)) << 4);
    #pragma unroll
    for (int j = 0; j < 4; j++)
        bOff[j] = 16384 + (tid >> 1) * 128 + (((bcb + j) ^ ((tid >> 1) & 7)) << 4);

    const int T = KD / KSTG;

    // prologue: stages 0..NSTAGE-2
    #pragma unroll
    for (int t = 0; t < NSTAGE - 1; t++) {
        uint32_t so = sb + t * STAGE_BYTES;
        const __half* ga = aSrc + t * KSTG;
        const __half* gb = bSrc + t * KSTG;
        #pragma unroll
        for (int j = 0; j < 2; j++) cpasync16(so + aOff[j], ga + (acb + j) * 8);
        #pragma unroll
        for (int j = 0; j < 4; j++) cpasync16(so + bOff[j], gb + (bcb + j) * 8);
        asm volatile("cp.async.commit_group;" ::: "memory");
    }

    // ---- compute mapping (ldmatrix lane geometry)
    const int wid = tid >> 5, lane = tid & 31;
    const int wm = wid >> 2, wn = wid & 3;          // 4x4 warps of 32x64
    const int mat = lane >> 3;
    const int l8  = ((mat & 1) << 3) + (lane & 7);  // row-within-16
    const int cm  = mat >> 1;                       // 16B chunk sub-index
    const int rsw = l8 & 7;                         // reader swizzle
    uint32_t pc[4];
    #pragma unroll
    for (int kb = 0; kb < 4; kb++) pc[kb] = (uint32_t)(((2 * kb + cm) ^ rsw) << 4);
    const uint32_t aLane = (uint32_t)(wm * 4096 + l8 * 128);
    const uint32_t bLane = (uint32_t)(16384 + wn * 8192 + l8 * 128);

    float acc[2][8][4];
    #pragma unroll
    for (int i = 0; i < 2; i++)
        #pragma unroll
        for (int j = 0; j < 8; j++)
            #pragma unroll
            for (int q = 0; q < 4; q++) acc[i][j][q] = 0.f;

    for (int jt = 0; jt < T; jt++) {
        if (jt < T - 2)       asm volatile("cp.async.wait_group 2;" ::: "memory");
        else if (jt == T - 2) asm volatile("cp.async.wait_group 1;" ::: "memory");
        else                  asm volatile("cp.async.wait_group 0;" ::: "memory");
        __syncthreads();

        if (jt + NSTAGE - 1 < T) {
            int t = jt + NSTAGE - 1;
            uint32_t so = sb + (t & (NSTAGE - 1)) * STAGE_BYTES;
            const __half* ga = aSrc + t * KSTG;
            const __half* gb = bSrc + t * KSTG;
            #pragma unroll
            for (int j = 0; j < 2; j++) cpasync16(so + aOff[j], ga + (acb + j) * 8);
            #pragma unroll
            for (int j = 0; j < 4; j++) cpasync16(so + bOff[j], gb + (bcb + j) * 8);
            asm volatile("cp.async.commit_group;" ::: "memory");
        }

        const uint32_t so = sb + (jt & (NSTAGE - 1)) * STAGE_BYTES;
        const uint32_t sA = so + aLane;
        const uint32_t sB = so + bLane;

        #pragma unroll
        for (int kb = 0; kb < 4; kb++) {
            const uint32_t c = pc[kb];
            uint32_t a[2][4], b[8][2];
            #pragma unroll
            for (int mt = 0; mt < 2; mt++)
                ldsm4(a[mt][0], a[mt][1], a[mt][2], a[mt][3], sA + mt * 2048 + c);
            #pragma unroll
            for (int p = 0; p < 4; p++) {
                uint32_t r0, r1, r2, r3;
                ldsm4(r0, r1, r2, r3, sB + p * 2048 + c);
                b[2 * p][0]     = r0;
                b[2 * p + 1][0] = r1;
                b[2 * p][1]     = r2;
                b[2 * p + 1][1] = r3;
            }
            #pragma unroll
            for (int mt = 0; mt < 2; mt++)
                #pragma unroll
                for (int nt = 0; nt < 8; nt++)
                    mma_f16(acc[mt][nt], a[mt], b[nt]);
        }
    }

    // ---- epilogue. Frag: c0,c1 -> row qr cols 2qc,2qc+1; c2,c3 -> row qr+8
    const int qr = lane >> 2, qc = lane & 3;
    #pragma unroll
    for (int mt = 0; mt < 2; mt++) {
        const int r0 = rowBase + wm * 32 + mt * 16 + qr;
        const int r1 = r0 + 8;
        if (MODE == 0) {
            #pragma unroll
            for (int nt = 0; nt < 8; nt++) {
                const int cg = colBase + wn * 64 + nt * 8 + 2 * qc;
                float t0 = fmaxf(acc[mt][nt][0], 0.f);
                float t1 = fmaxf(acc[mt][nt][1], 0.f);
                float t2 = fmaxf(acc[mt][nt][2], 0.f);
                float t3 = fmaxf(acc[mt][nt][3], 0.f);
                *(__half2*)(g_Hh + (size_t)r0 * HDIM + cg) = __floats2half2_rn(t0 * t0, t1 * t1);
                *(__half2*)(g_Hh + (size_t)r1 * HDIM + cg) = __floats2half2_rn(t2 * t2, t3 * t3);
            }
        } else {
            int   tok0 = g_rowTok[r0],  tok1 = g_rowTok[r1];
            float w0   = g_rowW[r0],    w1   = g_rowW[r1];
            int   sl0  = g_rowSlot[r0], sl1  = g_rowSlot[r1];
            #pragma unroll
            for (int nt = 0; nt < 8; nt++) {
                const int cg = colBase + wn * 64 + nt * 8 + 2 * qc;
                if (tok0 >= 0)
                    *(float2*)(g_ys + (size_t)sl0 * DIM + cg) =
                        make_float2(w0 * acc[mt][nt][0], w0 * acc[mt][nt][1]);
                if (tok1 >= 0)
                    *(float2*)(g_ys + (size_t)sl1 * DIM + cg) =
                        make_float2(w1 * acc[mt][nt][2], w1 * acc[mt][nt][3]);
            }
        }
    }
}

// ---------------- K6: combine two slots per token ---------------------------
__global__ void k_combine(float* __restrict__ out) {
    int i = blockIdx.x * blockDim.x + threadIdx.x;
    const int PR = DIM / 4;
    if (i >= N_TOK * PR) return;
    int n = i / PR;
    int c = i - n * PR;
    const float4* ys = (const float4*)g_ys;
    float4 a = ys[(size_t)(2 * n) * PR + c];
    float4 b = ys[(size_t)(2 * n + 1) * PR + c];
    float4 o;
    o.x = a.x + b.x; o.y = a.y + b.y; o.z = a.z + b.z; o.w = a.w + b.w;
    ((float4*)out)[(size_t)n * PR + c] = o;
}

// ---------------------------------------------------------------------------
extern "C" void kernel_launch(void* const* d_in, const int* in_sizes, int n_in,
                              void* d_out, int out_size) {
    const float* x   = (const float*)d_in[0];   // [8192, 1024]
    const float* gw  = (const float*)d_in[1];   // [8, 1024]
    const float* wfc = (const float*)d_in[2];   // [8, 4096, 1024]
    const float* wpj = (const float*)d_in[3];   // [8, 1024, 4096]
    float* out = (float*)d_out;

    const int SMEM_BYTES = NSTAGE * STAGE_BYTES;   // 196608
    cudaFuncSetAttribute(k_mma<DIM, 0>,  cudaFuncAttributeMaxDynamicSharedMemorySize, SMEM_BYTES);
    cudaFuncSetAttribute(k_mma<HDIM, 1>, cudaFuncAttributeMaxDynamicSharedMemorySize, SMEM_BYTES);

    // fp32 -> fp16 conversions
    __half *xh, *wfh, *wph;
    cudaGetSymbolAddress((void**)&xh,  g_xh);
    cudaGetSymbolAddress((void**)&wfh, g_wfch);
    cudaGetSymbolAddress((void**)&wph, g_wpjh);
    {
        int n4 = N_TOK * DIM / 4;
        k_half<<<(n4 + 255) / 256, 256>>>((const float4*)x, (uint2*)xh, n4);
        n4 = NEXP * HDIM * DIM / 4;
        k_half<<<(n4 + 255) / 256, 256>>>((const float4*)wfc, (uint2*)wfh, n4);
        k_half<<<(n4 + 255) / 256, 256>>>((const float4*)wpj, (uint2*)wph, n4);
    }

    k_init<<<CAP / 256, 256>>>();
    k_gate<<<N_TOK / 8, 256>>>(x, gw);
    k_scan<<<1, 32>>>(out, out_size);
    k_scatter<<<NSLOT / 256, 256>>>();

    dim3 g1(HDIM / BN, MAXTILES);               // 16 x 136
    k_mma<DIM, 0><<<g1, NTHR, SMEM_BYTES>>>(xh, wfh);

    dim3 g2(DIM / BN, MAXTILES);                // 4 x 136
    k_mma<HDIM, 1><<<g2, NTHR, SMEM_BYTES>>>(nullptr, wph);

    k_combine<<<(N_TOK * (DIM / 4) + 255) / 256, 256>>>(out);
}